// round 14
// baseline (speedup 1.0000x reference)
#include <cuda_runtime.h>
#include <cuda_fp16.h>
#include <math.h>

#define LL   16384
#define KTL  4096
#define NB   32
#define NT   50
#define NTH  512

// compact twiddle tables (identity: tw_big[j+q0*MS] = tw_base[j]*C[q0])
#define T1024S 0
#define T1024B 1024
#define T64S   2048
#define T64B   2112
#define T4S    2176
#define T4B    2180
#define TWTOT  2184

// ---------------- device scratch ----------------
__device__ float2  g_S[2][LL];        // S spectra (fp32)
__device__ __half2 g_H[100][LL];      // H' = S*H template spectra (fp16 complex)
__device__ __half2 g_D[64][LL];       // Xi spectra (fp16 complex)
__device__ float   g_z[NB * 2 * NT];
__device__ float2  g_twf[TWTOT];
__device__ int     g_done = 0;        // k_inv completion counter (self-resetting)

// swizzle for fp16 (4B) workspace (conflict-free for strides 1,4,64,1024;
// preserves low 2 bits => 16B vector ld/st stay contiguous)
#define SWH(k) ((k) ^ ((((k) >> 6) & 7) << 2))

// ---------------- complex helpers ----------------
__device__ __forceinline__ float2 cadd(float2 a, float2 b) { return make_float2(a.x + b.x, a.y + b.y); }
__device__ __forceinline__ float2 csub(float2 a, float2 b) { return make_float2(a.x - b.x, a.y - b.y); }
__device__ __forceinline__ float2 cmul(float2 a, float2 b) {
    return make_float2(a.x * b.x - a.y * b.y, a.x * b.y + a.y * b.x);
}
__device__ __forceinline__ float2 cmulcj(float2 a, float2 b) {  // a * conj(b)
    return make_float2(a.x * b.x + a.y * b.y, a.y * b.x - a.x * b.y);
}

// C[q0] = exp(-2*pi*i*q0/16)
__device__ __forceinline__ float2 c16(int q0) {
    if (q0 == 1) return make_float2(0.9238795325112867f, -0.3826834323650898f);
    if (q0 == 2) return make_float2(0.7071067811865476f, -0.7071067811865476f);
    return make_float2(0.3826834323650898f, -0.9238795325112867f);
}

// load 4 consecutive fp16 complex values as float2 (one 16B load)
__device__ __forceinline__ void ld4h(const __half2* __restrict__ p, float2 v[4]) {
    uint4 u = *reinterpret_cast<const uint4*>(p);
    v[0] = __half22float2(*reinterpret_cast<__half2*>(&u.x));
    v[1] = __half22float2(*reinterpret_cast<__half2*>(&u.y));
    v[2] = __half22float2(*reinterpret_cast<__half2*>(&u.z));
    v[3] = __half22float2(*reinterpret_cast<__half2*>(&u.w));
}

__device__ __forceinline__ void st4h(__half2* __restrict__ p, float2 a, float2 b,
                                     float2 c, float2 d) {
    uint4 u;
    *reinterpret_cast<__half2*>(&u.x) = __floats2half2_rn(a.x, a.y);
    *reinterpret_cast<__half2*>(&u.y) = __floats2half2_rn(b.x, b.y);
    *reinterpret_cast<__half2*>(&u.z) = __floats2half2_rn(c.x, c.y);
    *reinterpret_cast<__half2*>(&u.w) = __floats2half2_rn(d.x, d.y);
    *reinterpret_cast<uint4*>(p) = u;
}

// forward DIF radix-4: butterfly then twiddle outputs
__device__ __forceinline__ void bf_fwd(float2& x0, float2& x1, float2& x2, float2& x3, float2 w1) {
    float2 p02 = cadd(x0, x2), m02 = csub(x0, x2);
    float2 p13 = cadd(x1, x3), m13 = csub(x1, x3);
    float2 ni  = make_float2(m13.y, -m13.x);
    float2 b0 = cadd(p02, p13), b1 = cadd(m02, ni);
    float2 b2 = csub(p02, p13), b3 = csub(m02, ni);
    float2 w2 = make_float2(w1.x * w1.x - w1.y * w1.y, 2.f * w1.x * w1.y);
    float2 w3 = cmul(w2, w1);
    x0 = b0; x1 = cmul(b1, w1); x2 = cmul(b2, w2); x3 = cmul(b3, w3);
}

// inverse DIT radix-4: conj-twiddle inputs then butterfly
__device__ __forceinline__ void bf_inv(float2& x0, float2& x1, float2& x2, float2& x3, float2 w1) {
    w1.y = -w1.y;
    float2 w2 = make_float2(w1.x * w1.x - w1.y * w1.y, 2.f * w1.x * w1.y);
    float2 w3 = cmul(w2, w1);
    float2 a1 = cmul(x1, w1), a2 = cmul(x2, w2), a3 = cmul(x3, w3);
    float2 p02 = cadd(x0, a2), m02 = csub(x0, a2);
    float2 p13 = cadd(a1, a3), m13 = csub(a1, a3);
    float2 pi  = make_float2(-m13.y, m13.x);
    x0 = cadd(p02, p13); x1 = cadd(m02, pi);
    x2 = csub(p02, p13); x3 = csub(m02, pi);
}

// ---------------- twiddle generation (fp32 sincospif — no DP pipe) ----------------
__device__ __forceinline__ float2 twval(int i) {
    int j; float den;
    if      (i < T1024B) { j = i;          den = 4096.f;  }
    else if (i < T64S)   { j = i - T1024B; den = 16384.f; }
    else if (i < T64B)   { j = i - T64S;   den = 256.f;   }
    else if (i < T4S)    { j = i - T64B;   den = 1024.f;  }
    else if (i < T4B)    { j = i - T4S;    den = 16.f;    }
    else                 { j = i - T4B;    den = 64.f;    }
    float a = -2.f * (float)j / den;
    float s, c;
    sincospif(a, &s, &c);
    return make_float2(c, s);
}

__device__ __forceinline__ void loadtw(float2* tw) {
    for (int k = threadIdx.x; k < TWTOT; k += NTH) tw[k] = g_twf[k];
}

// ---------------- forward radix-16 pass, fp16 workspace ----------------
template <int MS, int TSOF, int TBOF>
__device__ void pass16hf(__half2* __restrict__ s, const float2* __restrict__ tw) {
    const int tid = threadIdx.x;
#pragma unroll 1
    for (int i = 0; i < 2; i++) {
        const int tau  = tid + i * NTH;
        const int j    = tau & (MS - 1);
        const int g    = tau / MS;
        const int base = g * (16 * MS) + j;
        float2 x[16];
#pragma unroll
        for (int q = 0; q < 16; q++) x[q] = __half22float2(s[SWH(base + q * MS)]);
        float2 tb = tw[TBOF + j];
        bf_fwd(x[0], x[4], x[8], x[12], tb);
#pragma unroll
        for (int q0 = 1; q0 < 4; q0++) {
            float2 wb = cmul(tb, c16(q0));
            bf_fwd(x[q0], x[q0 + 4], x[q0 + 8], x[q0 + 12], wb);
        }
        float2 ws = tw[TSOF + j];
#pragma unroll
        for (int q1 = 0; q1 < 4; q1++)
            bf_fwd(x[4 * q1], x[4 * q1 + 1], x[4 * q1 + 2], x[4 * q1 + 3], ws);
#pragma unroll
        for (int q = 0; q < 16; q++)
            s[SWH(base + q * MS)] = __floats2half2_rn(x[q].x, x[q].y);
    }
    __syncthreads();
}

__device__ __forceinline__ void fwd_core_h(__half2* dat, const float2* tw) {
    pass16hf<1024, T1024S, T1024B>(dat, tw);
    pass16hf<64,   T64S,   T64B>(dat, tw);
    pass16hf<4,    T4S,    T4B>(dat, tw);
}

// final forward m=1 butterfly (twiddle = 1); 4 consecutive bins = one LDS.128
__device__ __forceinline__ void last_fwd_h(const __half2* dat, int k0, float2& b0, float2& b1,
                                           float2& b2, float2& b3) {
    float2 x[4];
    ld4h(dat + SWH(k0), x);
    float2 p02 = cadd(x[0], x[2]), m02 = csub(x[0], x[2]);
    float2 p13 = cadd(x[1], x[3]), m13 = csub(x[1], x[3]);
    float2 ni  = make_float2(m13.y, -m13.x);
    b0 = cadd(p02, p13); b1 = cadd(m02, ni);
    b2 = csub(p02, p13); b3 = csub(m02, ni);
}

// ---------------- inverse radix-16 pass, fp16 workspace ----------------
template <int MS, int TSOF, int TBOF>
__device__ void pass16h(__half2* __restrict__ s, const float2* __restrict__ tw) {
    const int tid = threadIdx.x;
#pragma unroll 1
    for (int i = 0; i < 2; i++) {
        const int tau  = tid + i * NTH;
        const int j    = tau & (MS - 1);
        const int g    = tau / MS;
        const int base = g * (16 * MS) + j;
        float2 x[16];
#pragma unroll
        for (int q = 0; q < 16; q++) x[q] = __half22float2(s[SWH(base + q * MS)]);
        float2 ws = tw[TSOF + j];
#pragma unroll
        for (int q1 = 0; q1 < 4; q1++)
            bf_inv(x[4 * q1], x[4 * q1 + 1], x[4 * q1 + 2], x[4 * q1 + 3], ws);
        float2 tb = tw[TBOF + j];
        bf_inv(x[0], x[4], x[8], x[12], tb);
#pragma unroll
        for (int q0 = 1; q0 < 4; q0++) {
            float2 wb = cmul(tb, c16(q0));
            bf_inv(x[q0], x[q0 + 4], x[q0 + 8], x[q0 + 12], wb);
        }
#pragma unroll
        for (int q = 0; q < 16; q++)
            s[SWH(base + q * MS)] = __floats2half2_rn(x[q].x, x[q].y);
    }
    __syncthreads();
}

// ---------------- k_S: twiddle gen (fp32, cheap) + S FFT (2 blocks) ----------------
__global__ void __launch_bounds__(NTH, 2) k_S(const float* __restrict__ Sm) {
    extern __shared__ char smraw[];
    __half2* dat = (__half2*)smraw;
    float2*  tw  = (float2*)(smraw + (size_t)LL * 4);
    const int tid = threadIdx.x, bi = blockIdx.x;
    for (int i = tid; i < TWTOT; i += NTH) {
        float2 v = twval(i);
        tw[i] = v;
        g_twf[i] = v;
    }
    const float* src = Sm + bi * LL;
    for (int t = tid; t < LL; t += NTH)
        dat[SWH(t)] = __floats2half2_rn(src[t], 0.f);
    __syncthreads();
    fwd_core_h(dat, tw);
    float2* out = g_S[bi];
#pragma unroll 1
    for (int i = 0; i < 8; i++) {
        const int k0 = 4 * (tid + i * NTH);
        float2 b0, b1, b2, b3;
        last_fwd_h(dat, k0, b0, b1, b2, b3);
        float4* o4 = (float4*)(out + k0);
        o4[0] = make_float4(b0.x, b0.y, b1.x, b1.y);
        o4[1] = make_float4(b2.x, b2.y, b3.x, b3.y);
    }
}

// ---------------- k_fwd: templates (100 blocks, H' = S*H) + xi (64 blocks) ----------------
__global__ void __launch_bounds__(NTH, 2) k_fwd(const float* __restrict__ Tm,
                                                const float* __restrict__ xi) {
    extern __shared__ char smraw[];
    __half2* dat = (__half2*)smraw;
    float2*  tw  = (float2*)(smraw + (size_t)LL * 4);
    const int tid = threadIdx.x, bi = blockIdx.x;
    loadtw(tw);
    if (bi < 100) {
        const float* src = Tm + (size_t)bi * KTL;
        for (int t = tid; t < LL; t += NTH)
            dat[SWH(t)] = __floats2half2_rn(t < KTL ? src[t] : 0.f, 0.f);
    } else {
        const float* src = xi + (size_t)(bi - 100) * LL;
        for (int t = tid; t < LL; t += NTH)
            dat[SWH(t)] = __floats2half2_rn(src[t], 0.f);
    }
    __syncthreads();
    fwd_core_h(dat, tw);
    if (bi < 100) {
        const float2* Sc = g_S[bi & 1];
        __half2* out = g_H[bi];
#pragma unroll 1
        for (int i = 0; i < 8; i++) {
            const int k0 = 4 * (tid + i * NTH);
            float2 b0, b1, b2, b3;
            last_fwd_h(dat, k0, b0, b1, b2, b3);
            const float4* s4 = (const float4*)(Sc + k0);
            float4 sA = s4[0], sB = s4[1];
            st4h(out + k0,
                 cmul(b0, make_float2(sA.x, sA.y)),
                 cmul(b1, make_float2(sA.z, sA.w)),
                 cmul(b2, make_float2(sB.x, sB.y)),
                 cmul(b3, make_float2(sB.z, sB.w)));
        }
    } else {
        __half2* out = g_D[bi - 100];
#pragma unroll 1
        for (int i = 0; i < 8; i++) {
            const int k0 = 4 * (tid + i * NTH);
            float2 b0, b1, b2, b3;
            last_fwd_h(dat, k0, b0, b1, b2, b3);
            st4h(out + k0, b0, b1, b2, b3);
        }
    }
}

// ---------------- inverse + fused head (last block) ----------------
__device__ __forceinline__ float sigm(float x) { return 1.f / (1.f + __expf(-x)); }

__global__ void __launch_bounds__(NTH, 2) k_inv(
    const float* __restrict__ hh,
    const float* __restrict__ W1, const float* __restrict__ b1,
    const float* __restrict__ W2, const float* __restrict__ b2,
    const float* __restrict__ W3, const float* __restrict__ b3,
    const float* __restrict__ W4, const float* __restrict__ b4,
    float* __restrict__ out) {
    extern __shared__ char smraw[];
    __half2* dat = (__half2*)smraw;                     // 64 KB
    float2*  tw  = (float2*)(smraw + (size_t)LL * 4);  // 17.5 KB
    const int tid = threadIdx.x;
    const int n = blockIdx.x, b = blockIdx.y;
    loadtw(tw);
    const __half2* __restrict__ D0 = g_D[b * 2 + 0];
    const __half2* __restrict__ D1 = g_D[b * 2 + 1];
    const __half2* __restrict__ H0 = g_H[n * 2 + 0];
    const __half2* __restrict__ H1 = g_H[n * 2 + 1];
    // pointwise spectral product (pack: GA + i*GE) fused with inverse m=1 stage
#pragma unroll 1
    for (int i = 0; i < 8; i++) {
        const int k0 = 4 * (tid + i * NTH);
        float2 d[4], e[4], h[4], f[4];
        ld4h(D0 + k0, d);
        ld4h(D1 + k0, e);
        ld4h(H0 + k0, h);
        ld4h(H1 + k0, f);
        float2 v[4];
#pragma unroll
        for (int q = 0; q < 4; q++) {
            float2 GA = cmulcj(d[q], h[q]);
            float2 GE = cmulcj(e[q], f[q]);
            v[q] = make_float2(GA.x - GE.y, GA.y + GE.x);
        }
        float2 p02 = cadd(v[0], v[2]), m02 = csub(v[0], v[2]);
        float2 p13 = cadd(v[1], v[3]), m13 = csub(v[1], v[3]);
        float2 pi  = make_float2(-m13.y, m13.x);
        st4h(dat + SWH(k0), cadd(p02, p13), cadd(m02, pi),
             csub(p02, p13), csub(m02, pi));
    }
    __syncthreads();
    pass16h<4,  T4S,  T4B>(dat, tw);
    pass16h<64, T64S, T64B>(dat, tw);
    // last pass (1024,4096) in registers, fold max
    float mA = -3.4e38f, mE = -3.4e38f;
#pragma unroll 1
    for (int i = 0; i < 2; i++) {
        const int j = tid + i * NTH;
        float2 x[16];
#pragma unroll
        for (int q = 0; q < 16; q++) x[q] = __half22float2(dat[SWH(j + q * 1024)]);
        float2 ws = tw[T1024S + j];
#pragma unroll
        for (int q1 = 0; q1 < 4; q1++)
            bf_inv(x[4 * q1], x[4 * q1 + 1], x[4 * q1 + 2], x[4 * q1 + 3], ws);
        float2 tb = tw[T1024B + j];
        bf_inv(x[0], x[4], x[8], x[12], tb);
#pragma unroll
        for (int q0 = 1; q0 < 4; q0++) {
            float2 wb = cmul(tb, c16(q0));
            bf_inv(x[q0], x[q0 + 4], x[q0 + 8], x[q0 + 12], wb);
        }
#pragma unroll
        for (int q = 0; q < 16; q++) {
            mA = fmaxf(mA, x[q].x);
            mE = fmaxf(mE, x[q].y);
        }
    }
#pragma unroll
    for (int o = 16; o > 0; o >>= 1) {
        mA = fmaxf(mA, __shfl_xor_sync(0xffffffffu, mA, o));
        mE = fmaxf(mE, __shfl_xor_sync(0xffffffffu, mE, o));
    }
    __shared__ float rA[NTH / 32], rE[NTH / 32];
    __shared__ int s_last;
    if ((tid & 31) == 0) { rA[tid >> 5] = mA; rE[tid >> 5] = mE; }
    __syncthreads();
    if (tid == 0) {
        for (int i = 1; i < NTH / 32; i++) { mA = fmaxf(mA, rA[i]); mE = fmaxf(mE, rE[i]); }
        const float sc = 1.f / (float)LL;
        g_z[(b * 2 + 0) * NT + n] = mA * sc / hh[n * 2 + 0];
        g_z[(b * 2 + 1) * NT + n] = mE * sc / hh[n * 2 + 1];
        __threadfence();
        int old = atomicAdd(&g_done, 1);
        s_last = (old == NB * NT - 1) ? 1 : 0;
    }
    __syncthreads();

    // ---- last block: run the CNN/MLP head for all batches ----
    if (s_last) {
        __threadfence();  // acquire: make all g_z writes visible
        float* hs = (float*)smraw;              // reuse workspace (69.6 KB used)
        const int grp  = tid >> 4;              // 32 groups = 32 batches
        const int lane = tid & 15;              // 16 threads per group (half-warp)
        const unsigned mask = (grp & 1) ? 0xFFFF0000u : 0x0000FFFFu;
        float* zb = hs + grp * 544;             // [2][50] flat (100)
        float* p1 = zb + 104;                   // [16][16]
        float* p2 = p1 + 256;                   // [32][4]
        float* h1 = p2 + 128;                   // [32]
        const int bb = grp;

        for (int i = lane; i < 100; i += 16) zb[i] = g_z[bb * 100 + i];
        __syncwarp(mask);
        // conv1 [16,2,3] + sigmoid + maxpool3 -> p1 (tp = lane)
        for (int o = 0; o < 16; o++) {
            const int tp = lane;
            float mx = -3.4e38f;
            for (int q = 0; q < 3; q++) {
                const int t = 3 * tp + q;
                float acc = b1[o];
                for (int c = 0; c < 2; c++)
                    for (int j = 0; j < 3; j++)
                        acc += zb[c * 50 + t + j] * W1[(o * 2 + c) * 3 + j];
                mx = fmaxf(mx, sigm(acc));
            }
            p1[o * 16 + tp] = mx;
        }
        __syncwarp(mask);
        // conv2 [32,16,3] + sigmoid + maxpool3 (14 -> 4) -> p2
        for (int i = lane; i < 128; i += 16) {
            const int o = i >> 2, tp = i & 3;
            float mx = -3.4e38f;
            for (int q = 0; q < 3; q++) {
                const int t = 3 * tp + q;
                float acc = b2[o];
                for (int ci = 0; ci < 16; ci++)
                    for (int j = 0; j < 3; j++)
                        acc += p1[ci * 16 + t + j] * W2[(o * 16 + ci) * 3 + j];
                mx = fmaxf(mx, sigm(acc));
            }
            p2[o * 4 + tp] = mx;
        }
        __syncwarp(mask);
        // fc1 (128 -> 32) + relu
        for (int i = lane; i < 32; i += 16) {
            float acc = b3[i];
            for (int k = 0; k < 128; k++) acc += p2[k] * W3[i * 128 + k];
            h1[i] = fmaxf(acc, 0.f);
        }
        __syncwarp(mask);
        // fc2 (32 -> 2)
        if (lane < 2) {
            float acc = b4[lane];
            for (int i = 0; i < 32; i++) acc += h1[i] * W4[lane * 32 + i];
            out[bb * 2 + lane] = acc;
        }
        __syncthreads();
        if (tid == 0) g_done = 0;   // reset for next graph replay
    }
}

// ---------------- launch ----------------
extern "C" void kernel_launch(void* const* d_in, const int* in_sizes, int n_in,
                              void* d_out, int out_size) {
    const float* xi = (const float*)d_in[0];
    const float* S  = (const float*)d_in[1];
    const float* Tm = (const float*)d_in[2];
    const float* hh = (const float*)d_in[3];
    const float* W1 = (const float*)d_in[4];
    const float* b1 = (const float*)d_in[5];
    const float* W2 = (const float*)d_in[6];
    const float* b2 = (const float*)d_in[7];
    const float* W3 = (const float*)d_in[8];
    const float* b3 = (const float*)d_in[9];
    const float* W4 = (const float*)d_in[10];
    const float* b4 = (const float*)d_in[11];

    const size_t shi = (size_t)LL * 4 + (size_t)TWTOT * sizeof(float2);  // ~81.5 KB
    cudaFuncSetAttribute(k_S,   cudaFuncAttributeMaxDynamicSharedMemorySize, (int)shi);
    cudaFuncSetAttribute(k_fwd, cudaFuncAttributeMaxDynamicSharedMemorySize, (int)shi);
    cudaFuncSetAttribute(k_inv, cudaFuncAttributeMaxDynamicSharedMemorySize, (int)shi);

    k_S<<<2, NTH, shi>>>(S);
    k_fwd<<<164, NTH, shi>>>(Tm, xi);
    dim3 gi(NT, NB);
    k_inv<<<gi, NTH, shi>>>(hh, W1, b1, W2, b2, W3, b3, W4, b4, (float*)d_out);
}

// round 15
// speedup vs baseline: 1.5977x; 1.5977x over previous
#include <cuda_runtime.h>
#include <cuda_fp16.h>
#include <math.h>

#define LL   16384
#define KTL  4096
#define NB   32
#define NT   50
#define NTH  512

// compact twiddle tables (identity: tw_big[j+q0*MS] = tw_base[j]*C[q0])
#define T1024S 0
#define T1024B 1024
#define T64S   2048
#define T64B   2112
#define T4S    2176
#define T4B    2180
#define TWTOT  2184

// ---------------- device scratch ----------------
__device__ float2  g_S[2][LL];        // S spectra (fp32)
__device__ __half2 g_H[100][LL];      // H' = S*H template spectra (fp16 complex)
__device__ __half2 g_D[64][LL];       // Xi spectra (fp16 complex)
__device__ float   g_z[NB * 2 * NT];
__device__ float2  g_twf[TWTOT];
__device__ int     g_Sdone = 0;       // S-spectra completion counter (reset by k_inv)

// swizzle for fp16 (4B) workspace (conflict-free for strides 1,4,64,1024;
// preserves low 2 bits => 16B vector ld/st stay contiguous)
#define SWH(k) ((k) ^ ((((k) >> 6) & 7) << 2))

// ---------------- complex helpers ----------------
__device__ __forceinline__ float2 cadd(float2 a, float2 b) { return make_float2(a.x + b.x, a.y + b.y); }
__device__ __forceinline__ float2 csub(float2 a, float2 b) { return make_float2(a.x - b.x, a.y - b.y); }
__device__ __forceinline__ float2 cmul(float2 a, float2 b) {
    return make_float2(a.x * b.x - a.y * b.y, a.x * b.y + a.y * b.x);
}
__device__ __forceinline__ float2 cmulcj(float2 a, float2 b) {  // a * conj(b)
    return make_float2(a.x * b.x + a.y * b.y, a.y * b.x - a.x * b.y);
}

// C[q0] = exp(-2*pi*i*q0/16)
__device__ __forceinline__ float2 c16(int q0) {
    if (q0 == 1) return make_float2(0.9238795325112867f, -0.3826834323650898f);
    if (q0 == 2) return make_float2(0.7071067811865476f, -0.7071067811865476f);
    return make_float2(0.3826834323650898f, -0.9238795325112867f);
}

// load 4 consecutive fp16 complex values as float2 (one 16B load)
__device__ __forceinline__ void ld4h(const __half2* __restrict__ p, float2 v[4]) {
    uint4 u = *reinterpret_cast<const uint4*>(p);
    v[0] = __half22float2(*reinterpret_cast<__half2*>(&u.x));
    v[1] = __half22float2(*reinterpret_cast<__half2*>(&u.y));
    v[2] = __half22float2(*reinterpret_cast<__half2*>(&u.z));
    v[3] = __half22float2(*reinterpret_cast<__half2*>(&u.w));
}

__device__ __forceinline__ void st4h(__half2* __restrict__ p, float2 a, float2 b,
                                     float2 c, float2 d) {
    uint4 u;
    *reinterpret_cast<__half2*>(&u.x) = __floats2half2_rn(a.x, a.y);
    *reinterpret_cast<__half2*>(&u.y) = __floats2half2_rn(b.x, b.y);
    *reinterpret_cast<__half2*>(&u.z) = __floats2half2_rn(c.x, c.y);
    *reinterpret_cast<__half2*>(&u.w) = __floats2half2_rn(d.x, d.y);
    *reinterpret_cast<uint4*>(p) = u;
}

// forward DIF radix-4: butterfly then twiddle outputs
__device__ __forceinline__ void bf_fwd(float2& x0, float2& x1, float2& x2, float2& x3, float2 w1) {
    float2 p02 = cadd(x0, x2), m02 = csub(x0, x2);
    float2 p13 = cadd(x1, x3), m13 = csub(x1, x3);
    float2 ni  = make_float2(m13.y, -m13.x);
    float2 b0 = cadd(p02, p13), b1 = cadd(m02, ni);
    float2 b2 = csub(p02, p13), b3 = csub(m02, ni);
    float2 w2 = make_float2(w1.x * w1.x - w1.y * w1.y, 2.f * w1.x * w1.y);
    float2 w3 = cmul(w2, w1);
    x0 = b0; x1 = cmul(b1, w1); x2 = cmul(b2, w2); x3 = cmul(b3, w3);
}

// inverse DIT radix-4: conj-twiddle inputs then butterfly
__device__ __forceinline__ void bf_inv(float2& x0, float2& x1, float2& x2, float2& x3, float2 w1) {
    w1.y = -w1.y;
    float2 w2 = make_float2(w1.x * w1.x - w1.y * w1.y, 2.f * w1.x * w1.y);
    float2 w3 = cmul(w2, w1);
    float2 a1 = cmul(x1, w1), a2 = cmul(x2, w2), a3 = cmul(x3, w3);
    float2 p02 = cadd(x0, a2), m02 = csub(x0, a2);
    float2 p13 = cadd(a1, a3), m13 = csub(a1, a3);
    float2 pi  = make_float2(-m13.y, m13.x);
    x0 = cadd(p02, p13); x1 = cadd(m02, pi);
    x2 = csub(p02, p13); x3 = csub(m02, pi);
}

// ---------------- twiddle generation (fp32 sincospif — no DP pipe) ----------------
__device__ __forceinline__ float2 twval(int i) {
    int j; float den;
    if      (i < T1024B) { j = i;          den = 4096.f;  }
    else if (i < T64S)   { j = i - T1024B; den = 16384.f; }
    else if (i < T64B)   { j = i - T64S;   den = 256.f;   }
    else if (i < T4S)    { j = i - T64B;   den = 1024.f;  }
    else if (i < T4B)    { j = i - T4S;    den = 16.f;    }
    else                 { j = i - T4B;    den = 64.f;    }
    float a = -2.f * (float)j / den;
    float s, c;
    sincospif(a, &s, &c);
    return make_float2(c, s);
}

__device__ __forceinline__ void loadtw(float2* tw) {
    for (int k = threadIdx.x; k < TWTOT; k += NTH) tw[k] = g_twf[k];
}

// ---------------- forward radix-16 pass, fp16 workspace ----------------
template <int MS, int TSOF, int TBOF>
__device__ void pass16hf(__half2* __restrict__ s, const float2* __restrict__ tw) {
    const int tid = threadIdx.x;
#pragma unroll 1
    for (int i = 0; i < 2; i++) {
        const int tau  = tid + i * NTH;
        const int j    = tau & (MS - 1);
        const int g    = tau / MS;
        const int base = g * (16 * MS) + j;
        float2 x[16];
#pragma unroll
        for (int q = 0; q < 16; q++) x[q] = __half22float2(s[SWH(base + q * MS)]);
        float2 tb = tw[TBOF + j];
        bf_fwd(x[0], x[4], x[8], x[12], tb);
#pragma unroll
        for (int q0 = 1; q0 < 4; q0++) {
            float2 wb = cmul(tb, c16(q0));
            bf_fwd(x[q0], x[q0 + 4], x[q0 + 8], x[q0 + 12], wb);
        }
        float2 ws = tw[TSOF + j];
#pragma unroll
        for (int q1 = 0; q1 < 4; q1++)
            bf_fwd(x[4 * q1], x[4 * q1 + 1], x[4 * q1 + 2], x[4 * q1 + 3], ws);
#pragma unroll
        for (int q = 0; q < 16; q++)
            s[SWH(base + q * MS)] = __floats2half2_rn(x[q].x, x[q].y);
    }
    __syncthreads();
}

__device__ __forceinline__ void fwd_core_h(__half2* dat, const float2* tw) {
    pass16hf<1024, T1024S, T1024B>(dat, tw);
    pass16hf<64,   T64S,   T64B>(dat, tw);
    pass16hf<4,    T4S,    T4B>(dat, tw);
}

// final forward m=1 butterfly (twiddle = 1); 4 consecutive bins = one LDS.128
__device__ __forceinline__ void last_fwd_h(const __half2* dat, int k0, float2& b0, float2& b1,
                                           float2& b2, float2& b3) {
    float2 x[4];
    ld4h(dat + SWH(k0), x);
    float2 p02 = cadd(x[0], x[2]), m02 = csub(x[0], x[2]);
    float2 p13 = cadd(x[1], x[3]), m13 = csub(x[1], x[3]);
    float2 ni  = make_float2(m13.y, -m13.x);
    b0 = cadd(p02, p13); b1 = cadd(m02, ni);
    b2 = csub(p02, p13); b3 = csub(m02, ni);
}

// ---------------- inverse radix-16 pass, fp16 workspace ----------------
template <int MS, int TSOF, int TBOF>
__device__ void pass16h(__half2* __restrict__ s, const float2* __restrict__ tw) {
    const int tid = threadIdx.x;
#pragma unroll 1
    for (int i = 0; i < 2; i++) {
        const int tau  = tid + i * NTH;
        const int j    = tau & (MS - 1);
        const int g    = tau / MS;
        const int base = g * (16 * MS) + j;
        float2 x[16];
#pragma unroll
        for (int q = 0; q < 16; q++) x[q] = __half22float2(s[SWH(base + q * MS)]);
        float2 ws = tw[TSOF + j];
#pragma unroll
        for (int q1 = 0; q1 < 4; q1++)
            bf_inv(x[4 * q1], x[4 * q1 + 1], x[4 * q1 + 2], x[4 * q1 + 3], ws);
        float2 tb = tw[TBOF + j];
        bf_inv(x[0], x[4], x[8], x[12], tb);
#pragma unroll
        for (int q0 = 1; q0 < 4; q0++) {
            float2 wb = cmul(tb, c16(q0));
            bf_inv(x[q0], x[q0 + 4], x[q0 + 8], x[q0 + 12], wb);
        }
#pragma unroll
        for (int q = 0; q < 16; q++)
            s[SWH(base + q * MS)] = __floats2half2_rn(x[q].x, x[q].y);
    }
    __syncthreads();
}

// ---------------- k_all: S (2) + templates (100, wait on S) + xi (64) ----------------
// 166 blocks <= 296 resident slots -> all co-resident, spin-wait cannot deadlock.
__global__ void __launch_bounds__(NTH, 2) k_all(const float* __restrict__ Tm,
                                                const float* __restrict__ xi,
                                                const float* __restrict__ Sm) {
    extern __shared__ char smraw[];
    __half2* dat = (__half2*)smraw;
    float2*  tw  = (float2*)(smraw + (size_t)LL * 4);
    __shared__ int s_ok;
    const int tid = threadIdx.x, bi = blockIdx.x;
    const bool isS = (bi >= 164);

    // every block computes its twiddles locally (fp32, ~4 sincospif/thread);
    // S blocks also publish them for k_inv
    for (int i = tid; i < TWTOT; i += NTH) {
        float2 v = twval(i);
        tw[i] = v;
        if (isS) g_twf[i] = v;
    }
    if (bi < 100) {
        const float* src = Tm + (size_t)bi * KTL;
        for (int t = tid; t < LL; t += NTH)
            dat[SWH(t)] = __floats2half2_rn(t < KTL ? src[t] : 0.f, 0.f);
    } else if (bi < 164) {
        const float* src = xi + (size_t)(bi - 100) * LL;
        for (int t = tid; t < LL; t += NTH)
            dat[SWH(t)] = __floats2half2_rn(src[t], 0.f);
    } else {
        const float* src = Sm + (size_t)(bi - 164) * LL;
        for (int t = tid; t < LL; t += NTH)
            dat[SWH(t)] = __floats2half2_rn(src[t], 0.f);
    }
    __syncthreads();
    fwd_core_h(dat, tw);

    if (isS) {
        float2* out = g_S[bi - 164];
#pragma unroll 1
        for (int i = 0; i < 8; i++) {
            const int k0 = 4 * (tid + i * NTH);
            float2 b0, b1, b2, b3;
            last_fwd_h(dat, k0, b0, b1, b2, b3);
            float4* o4 = (float4*)(out + k0);
            o4[0] = make_float4(b0.x, b0.y, b1.x, b1.y);
            o4[1] = make_float4(b2.x, b2.y, b3.x, b3.y);
        }
        __threadfence();          // publish g_S (and g_twf) before signaling
        __syncthreads();
        if (tid == 0) atomicAdd(&g_Sdone, 1);
    } else if (bi >= 100) {
        __half2* out = g_D[bi - 100];
#pragma unroll 1
        for (int i = 0; i < 8; i++) {
            const int k0 = 4 * (tid + i * NTH);
            float2 b0, b1, b2, b3;
            last_fwd_h(dat, k0, b0, b1, b2, b3);
            st4h(out + k0, b0, b1, b2, b3);
        }
    } else {
        // template block: wait for both S spectra (S blocks run concurrently
        // and finish in parallel with our own FFT -> expected wait ~ 0)
        if (tid == 0) {
            while (*(volatile int*)&g_Sdone < 2) __nanosleep(40);
            s_ok = 1;
        }
        __syncthreads();
        __threadfence();          // acquire: order g_S reads after flag
        const float2* Sc = g_S[bi & 1];
        __half2* out = g_H[bi];
#pragma unroll 1
        for (int i = 0; i < 8; i++) {
            const int k0 = 4 * (tid + i * NTH);
            float2 b0, b1, b2, b3;
            last_fwd_h(dat, k0, b0, b1, b2, b3);
            const float4* s4 = (const float4*)(Sc + k0);
            float4 sA = s4[0], sB = s4[1];
            st4h(out + k0,
                 cmul(b0, make_float2(sA.x, sA.y)),
                 cmul(b1, make_float2(sA.z, sA.w)),
                 cmul(b2, make_float2(sB.x, sB.y)),
                 cmul(b3, make_float2(sB.z, sB.w)));
        }
    }
}

// ---------------- inverse: grid (NT, NB), one tile per block (R13 verbatim) ----------------
__global__ void __launch_bounds__(NTH, 2) k_inv(const float* __restrict__ hh) {
    extern __shared__ char smraw[];
    __half2* dat = (__half2*)smraw;                     // 64 KB
    float2*  tw  = (float2*)(smraw + (size_t)LL * 4);  // 17.5 KB
    const int tid = threadIdx.x;
    const int n = blockIdx.x, b = blockIdx.y;
    if (tid == 0 && n == 0 && b == 0) g_Sdone = 0;      // reset for next replay
    loadtw(tw);
    const __half2* __restrict__ D0 = g_D[b * 2 + 0];
    const __half2* __restrict__ D1 = g_D[b * 2 + 1];
    const __half2* __restrict__ H0 = g_H[n * 2 + 0];
    const __half2* __restrict__ H1 = g_H[n * 2 + 1];
    // pointwise spectral product (pack: GA + i*GE) fused with inverse m=1 stage
#pragma unroll 1
    for (int i = 0; i < 8; i++) {
        const int k0 = 4 * (tid + i * NTH);
        float2 d[4], e[4], h[4], f[4];
        ld4h(D0 + k0, d);
        ld4h(D1 + k0, e);
        ld4h(H0 + k0, h);
        ld4h(H1 + k0, f);
        float2 v[4];
#pragma unroll
        for (int q = 0; q < 4; q++) {
            float2 GA = cmulcj(d[q], h[q]);
            float2 GE = cmulcj(e[q], f[q]);
            v[q] = make_float2(GA.x - GE.y, GA.y + GE.x);
        }
        float2 p02 = cadd(v[0], v[2]), m02 = csub(v[0], v[2]);
        float2 p13 = cadd(v[1], v[3]), m13 = csub(v[1], v[3]);
        float2 pi  = make_float2(-m13.y, m13.x);
        st4h(dat + SWH(k0), cadd(p02, p13), cadd(m02, pi),
             csub(p02, p13), csub(m02, pi));
    }
    __syncthreads();
    pass16h<4,  T4S,  T4B>(dat, tw);
    pass16h<64, T64S, T64B>(dat, tw);
    // last pass (1024,4096) in registers, fold max
    float mA = -3.4e38f, mE = -3.4e38f;
#pragma unroll 1
    for (int i = 0; i < 2; i++) {
        const int j = tid + i * NTH;
        float2 x[16];
#pragma unroll
        for (int q = 0; q < 16; q++) x[q] = __half22float2(dat[SWH(j + q * 1024)]);
        float2 ws = tw[T1024S + j];
#pragma unroll
        for (int q1 = 0; q1 < 4; q1++)
            bf_inv(x[4 * q1], x[4 * q1 + 1], x[4 * q1 + 2], x[4 * q1 + 3], ws);
        float2 tb = tw[T1024B + j];
        bf_inv(x[0], x[4], x[8], x[12], tb);
#pragma unroll
        for (int q0 = 1; q0 < 4; q0++) {
            float2 wb = cmul(tb, c16(q0));
            bf_inv(x[q0], x[q0 + 4], x[q0 + 8], x[q0 + 12], wb);
        }
#pragma unroll
        for (int q = 0; q < 16; q++) {
            mA = fmaxf(mA, x[q].x);
            mE = fmaxf(mE, x[q].y);
        }
    }
#pragma unroll
    for (int o = 16; o > 0; o >>= 1) {
        mA = fmaxf(mA, __shfl_xor_sync(0xffffffffu, mA, o));
        mE = fmaxf(mE, __shfl_xor_sync(0xffffffffu, mE, o));
    }
    __shared__ float rA[NTH / 32], rE[NTH / 32];
    if ((tid & 31) == 0) { rA[tid >> 5] = mA; rE[tid >> 5] = mE; }
    __syncthreads();
    if (tid == 0) {
        for (int i = 1; i < NTH / 32; i++) { mA = fmaxf(mA, rA[i]); mE = fmaxf(mE, rE[i]); }
        const float sc = 1.f / (float)LL;
        g_z[(b * 2 + 0) * NT + n] = mA * sc / hh[n * 2 + 0];
        g_z[(b * 2 + 1) * NT + n] = mE * sc / hh[n * 2 + 1];
    }
}

// ---------------- tiny CNN + MLP head (R13 verbatim) ----------------
__device__ __forceinline__ float sigm(float x) { return 1.f / (1.f + __expf(-x)); }

__global__ void k_head(const float* __restrict__ W1, const float* __restrict__ b1,
                       const float* __restrict__ W2, const float* __restrict__ b2,
                       const float* __restrict__ W3, const float* __restrict__ b3,
                       const float* __restrict__ W4, const float* __restrict__ b4,
                       float* __restrict__ out) {
    __shared__ float zb[2][NT];
    __shared__ float sW1[96],  sb1[16];
    __shared__ float sW2[1536], sb2[32];
    __shared__ float sW3[4096], sb3[32];
    __shared__ float sW4[64],   sb4[2];
    __shared__ float p1[16][16];
    __shared__ float p2[32][4];
    __shared__ float h1[32];
    const int b = blockIdx.x, tid = threadIdx.x;

    for (int i = tid; i < 2 * NT; i += 128) zb[i / NT][i % NT] = g_z[b * 2 * NT + i];
    if (tid < 96) sW1[tid] = W1[tid];
    if (tid < 16) sb1[tid] = b1[tid];
    for (int i = tid; i < 1536; i += 128) sW2[i] = W2[i];
    if (tid < 32) sb2[tid] = b2[tid];
    for (int i = tid; i < 4096; i += 128) sW3[i] = W3[i];
    if (tid >= 32 && tid < 64) sb3[tid - 32] = b3[tid - 32];
    if (tid >= 64 && tid < 128) sW4[tid - 64] = W4[tid - 64];
    if (tid >= 96 && tid < 98) sb4[tid - 96] = b4[tid - 96];
    __syncthreads();

    for (int i = tid; i < 16 * 16; i += 128) {
        int o = i >> 4, tp = i & 15;
        float mx = -3.4e38f;
        for (int q = 0; q < 3; q++) {
            int t = 3 * tp + q;
            float acc = sb1[o];
            for (int c = 0; c < 2; c++)
                for (int j = 0; j < 3; j++) acc += zb[c][t + j] * sW1[(o * 2 + c) * 3 + j];
            mx = fmaxf(mx, sigm(acc));
        }
        p1[o][tp] = mx;
    }
    __syncthreads();
    for (int i = tid; i < 32 * 4; i += 128) {
        int o = i >> 2, tp = i & 3;
        float mx = -3.4e38f;
        for (int q = 0; q < 3; q++) {
            int t = 3 * tp + q;
            float acc = sb2[o];
            for (int ci = 0; ci < 16; ci++)
                for (int j = 0; j < 3; j++) acc += p1[ci][t + j] * sW2[(o * 16 + ci) * 3 + j];
            mx = fmaxf(mx, sigm(acc));
        }
        p2[o][tp] = mx;
    }
    __syncthreads();
    if (tid < 32) {
        float acc = sb3[tid];
        for (int i = 0; i < 128; i++) acc += p2[i >> 2][i & 3] * sW3[tid * 128 + i];
        h1[tid] = fmaxf(acc, 0.f);
    }
    __syncthreads();
    if (tid < 2) {
        float acc = sb4[tid];
        for (int i = 0; i < 32; i++) acc += h1[i] * sW4[tid * 32 + i];
        out[b * 2 + tid] = acc;
    }
}

// ---------------- launch ----------------
extern "C" void kernel_launch(void* const* d_in, const int* in_sizes, int n_in,
                              void* d_out, int out_size) {
    const float* xi = (const float*)d_in[0];
    const float* S  = (const float*)d_in[1];
    const float* Tm = (const float*)d_in[2];
    const float* hh = (const float*)d_in[3];
    const float* W1 = (const float*)d_in[4];
    const float* b1 = (const float*)d_in[5];
    const float* W2 = (const float*)d_in[6];
    const float* b2 = (const float*)d_in[7];
    const float* W3 = (const float*)d_in[8];
    const float* b3 = (const float*)d_in[9];
    const float* W4 = (const float*)d_in[10];
    const float* b4 = (const float*)d_in[11];

    const size_t shi = (size_t)LL * 4 + (size_t)TWTOT * sizeof(float2);  // ~81.5 KB
    cudaFuncSetAttribute(k_all, cudaFuncAttributeMaxDynamicSharedMemorySize, (int)shi);
    cudaFuncSetAttribute(k_inv, cudaFuncAttributeMaxDynamicSharedMemorySize, (int)shi);

    k_all<<<166, NTH, shi>>>(Tm, xi, S);
    dim3 gi(NT, NB);
    k_inv<<<gi, NTH, shi>>>(hh);
    k_head<<<NB, 128>>>(W1, b1, W2, b2, W3, b3, W4, b4, (float*)d_out);
}

// round 16
// speedup vs baseline: 1.8308x; 1.1459x over previous
#include <cuda_runtime.h>
#include <cuda_fp16.h>
#include <math.h>

#define LL   16384
#define KTL  4096
#define NB   32
#define NT   50
#define NTH  512

// compact twiddle tables (identity: tw_big[j+q0*MS] = tw_base[j]*C[q0])
#define T1024S 0
#define T1024B 1024
#define T64S   2048
#define T64B   2112
#define T4S    2176
#define T4B    2180
#define TWTOT  2184

// packed (broadcast-form) table entry indices for k_inv middle passes
#define E4S  0
#define E4B  4
#define E64S 8
#define E64B 72
#define EPTOT 136

// ---------------- device scratch ----------------
__device__ float2  g_S[2][LL];        // S spectra (fp32)
__device__ __half2 g_H[100][LL];      // H' = S*H template spectra (fp16 complex)
__device__ __half2 g_D[64][LL];       // Xi spectra (fp16 complex)
__device__ float   g_z[NB * 2 * NT];
__device__ float2  g_twf[TWTOT];
__device__ int     g_Sdone = 0;       // S-spectra completion counter (reset by k_inv)

// swizzle (conflict-free for strides 1,4,64,1024; preserves low 2 bits)
#define SWH(k) ((k) ^ ((((k) >> 6) & 7) << 2))

// ---------------- complex helpers (fp32) ----------------
__device__ __forceinline__ float2 cadd(float2 a, float2 b) { return make_float2(a.x + b.x, a.y + b.y); }
__device__ __forceinline__ float2 csub(float2 a, float2 b) { return make_float2(a.x - b.x, a.y - b.y); }
__device__ __forceinline__ float2 cmul(float2 a, float2 b) {
    return make_float2(a.x * b.x - a.y * b.y, a.x * b.y + a.y * b.x);
}
__device__ __forceinline__ float2 cmulcj(float2 a, float2 b) {  // a * conj(b)
    return make_float2(a.x * b.x + a.y * b.y, a.y * b.x - a.x * b.y);
}

// C[q0] = exp(-2*pi*i*q0/16)
__device__ __forceinline__ float2 c16(int q0) {
    if (q0 == 1) return make_float2(0.9238795325112867f, -0.3826834323650898f);
    if (q0 == 2) return make_float2(0.7071067811865476f, -0.7071067811865476f);
    return make_float2(0.3826834323650898f, -0.9238795325112867f);
}

// load 4 consecutive fp16 complex values as float2 (one 16B load)
__device__ __forceinline__ void ld4h(const __half2* __restrict__ p, float2 v[4]) {
    uint4 u = *reinterpret_cast<const uint4*>(p);
    v[0] = __half22float2(*reinterpret_cast<__half2*>(&u.x));
    v[1] = __half22float2(*reinterpret_cast<__half2*>(&u.y));
    v[2] = __half22float2(*reinterpret_cast<__half2*>(&u.z));
    v[3] = __half22float2(*reinterpret_cast<__half2*>(&u.w));
}

__device__ __forceinline__ void st4h(__half2* __restrict__ p, float2 a, float2 b,
                                     float2 c, float2 d) {
    uint4 u;
    *reinterpret_cast<__half2*>(&u.x) = __floats2half2_rn(a.x, a.y);
    *reinterpret_cast<__half2*>(&u.y) = __floats2half2_rn(b.x, b.y);
    *reinterpret_cast<__half2*>(&u.z) = __floats2half2_rn(c.x, c.y);
    *reinterpret_cast<__half2*>(&u.w) = __floats2half2_rn(d.x, d.y);
    *reinterpret_cast<uint4*>(p) = u;
}

// forward DIF radix-4: butterfly then twiddle outputs (fp32, k_all)
__device__ __forceinline__ void bf_fwd(float2& x0, float2& x1, float2& x2, float2& x3, float2 w1) {
    float2 p02 = cadd(x0, x2), m02 = csub(x0, x2);
    float2 p13 = cadd(x1, x3), m13 = csub(x1, x3);
    float2 ni  = make_float2(m13.y, -m13.x);
    float2 b0 = cadd(p02, p13), b1 = cadd(m02, ni);
    float2 b2 = csub(p02, p13), b3 = csub(m02, ni);
    float2 w2 = make_float2(w1.x * w1.x - w1.y * w1.y, 2.f * w1.x * w1.y);
    float2 w3 = cmul(w2, w1);
    x0 = b0; x1 = cmul(b1, w1); x2 = cmul(b2, w2); x3 = cmul(b3, w3);
}

// inverse DIT radix-4 (fp32, used by final pass)
__device__ __forceinline__ void bf_inv(float2& x0, float2& x1, float2& x2, float2& x3, float2 w1) {
    w1.y = -w1.y;
    float2 w2 = make_float2(w1.x * w1.x - w1.y * w1.y, 2.f * w1.x * w1.y);
    float2 w3 = cmul(w2, w1);
    float2 a1 = cmul(x1, w1), a2 = cmul(x2, w2), a3 = cmul(x3, w3);
    float2 p02 = cadd(x0, a2), m02 = csub(x0, a2);
    float2 p13 = cadd(a1, a3), m13 = csub(a1, a3);
    float2 pi  = make_float2(-m13.y, m13.x);
    x0 = cadd(p02, p13); x1 = cadd(m02, pi);
    x2 = csub(p02, p13); x3 = csub(m02, pi);
}

// ---------------- twiddle generation (fp32 sincospif) ----------------
__device__ __forceinline__ float2 twval(int i) {
    int j; float den;
    if      (i < T1024B) { j = i;          den = 4096.f;  }
    else if (i < T64S)   { j = i - T1024B; den = 16384.f; }
    else if (i < T64B)   { j = i - T64S;   den = 256.f;   }
    else if (i < T4S)    { j = i - T64B;   den = 1024.f;  }
    else if (i < T4B)    { j = i - T4S;    den = 16.f;    }
    else                 { j = i - T4B;    den = 64.f;    }
    float a = -2.f * (float)j / den;
    float s, c;
    sincospif(a, &s, &c);
    return make_float2(c, s);
}

__device__ __forceinline__ void loadtw(float2* tw) {
    for (int k = threadIdx.x; k < TWTOT; k += NTH) tw[k] = g_twf[k];
}

// ---------------- packed half2 butterfly machinery (k_inv middle passes) ----------------
// X holds (re_k, re_{k+8192}); Y holds (im_k, im_{k+8192}). Same twiddle for
// both lanes at every stage m <= 1024 (8192 % m == 0). All ops are 2-bin SIMD.

// forms F[9] = {RR,II,NII, RR2,II2,NII2, RR3,II3,NII3} (unconjugated w, w^2, w^3)
__device__ __forceinline__ void prep_forms(__half2* F, __half2 RR, __half2 II, __half2 NII) {
    F[0] = RR; F[1] = II; F[2] = NII;
    F[3] = __hfma2(II, NII, __hmul2(RR, RR));       // wr^2 - wi^2
    __half2 t = __hmul2(RR, II);
    F[4] = __hadd2(t, t);                           // 2 wr wi
    F[5] = __hneg2(F[4]);
    F[6] = __hfma2(F[4], NII, __hmul2(F[3], RR));   // w3 re
    F[7] = __hfma2(F[4], RR, __hmul2(F[3], II));    // w3 im
    F[8] = __hneg2(F[7]);
}

// inverse radix-4 butterfly on packed values, applying conj(w^q) twiddles.
template <int S>
__device__ __forceinline__ void bfp_inv(__half2* X, __half2* Y, const __half2 (&F)[9]) {
    // a_q = x_q * conj(w^q):  re' = re*wr + im*wi ; im' = im*wr - re*wi
    __half2 a1X = __hfma2(Y[S],     F[1], __hmul2(X[S],     F[0]));
    __half2 a1Y = __hfma2(X[S],     F[2], __hmul2(Y[S],     F[0]));
    __half2 a2X = __hfma2(Y[2 * S], F[4], __hmul2(X[2 * S], F[3]));
    __half2 a2Y = __hfma2(X[2 * S], F[5], __hmul2(Y[2 * S], F[3]));
    __half2 a3X = __hfma2(Y[3 * S], F[7], __hmul2(X[3 * S], F[6]));
    __half2 a3Y = __hfma2(X[3 * S], F[8], __hmul2(Y[3 * S], F[6]));
    __half2 p02X = __hadd2(X[0], a2X), p02Y = __hadd2(Y[0], a2Y);
    __half2 m02X = __hsub2(X[0], a2X), m02Y = __hsub2(Y[0], a2Y);
    __half2 p13X = __hadd2(a1X, a3X),  p13Y = __hadd2(a1Y, a3Y);
    __half2 m13X = __hsub2(a1X, a3X),  m13Y = __hsub2(a1Y, a3Y);
    // out1 = m02 + i*m13 ; out3 = m02 - i*m13
    X[0]     = __hadd2(p02X, p13X); Y[0]     = __hadd2(p02Y, p13Y);
    X[S]     = __hsub2(m02X, m13Y); Y[S]     = __hadd2(m02Y, m13X);
    X[2 * S] = __hsub2(p02X, p13X); Y[2 * S] = __hsub2(p02Y, p13Y);
    X[3 * S] = __hadd2(m02X, m13Y); Y[3 * S] = __hsub2(m02Y, m13X);
}

// one packed radix-16 pass (stages m=MS and m=4*MS) over the 8192-pair domain.
template <int MS, int ES, int EB>
__device__ void pass16p(__half2* __restrict__ Xa, __half2* __restrict__ Ya,
                        const __half2* __restrict__ twp) {
    const int tid  = threadIdx.x;
    const int j    = tid & (MS - 1);
    const int g    = tid / MS;
    const int base = g * (16 * MS) + j;
    __half2 XX[16], YY[16];
#pragma unroll
    for (int q = 0; q < 16; q++) {
        const int a = SWH(base + q * MS);
        XX[q] = Xa[a]; YY[q] = Ya[a];
    }
    {   // small stage (stride MS): one shared twiddle
        __half2 F[9];
        prep_forms(F, twp[3 * (ES + j)], twp[3 * (ES + j) + 1], twp[3 * (ES + j) + 2]);
        bfp_inv<1>(XX + 0,  YY + 0,  F);
        bfp_inv<1>(XX + 4,  YY + 4,  F);
        bfp_inv<1>(XX + 8,  YY + 8,  F);
        bfp_inv<1>(XX + 12, YY + 12, F);
    }
    {   // big stage (stride 4*MS): wb = base * c16(q0)
        __half2 BR = twp[3 * (EB + j)], BI = twp[3 * (EB + j) + 1], BNI = twp[3 * (EB + j) + 2];
        __half2 F[9];
        prep_forms(F, BR, BI, BNI);
        bfp_inv<4>(XX + 0, YY + 0, F);
#pragma unroll
        for (int q0 = 1; q0 < 4; q0++) {
            const float2 c = c16(q0);
            const __half2 CR  = __float2half2_rn(c.x);
            const __half2 CI  = __float2half2_rn(c.y);
            const __half2 NCI = __float2half2_rn(-c.y);
            __half2 RRb  = __hfma2(BI, NCI, __hmul2(BR, CR));
            __half2 IIb  = __hfma2(BR, CI,  __hmul2(BI, CR));
            __half2 NIIb = __hneg2(IIb);
            prep_forms(F, RRb, IIb, NIIb);
            bfp_inv<4>(XX + q0, YY + q0, F);
        }
    }
#pragma unroll
    for (int q = 0; q < 16; q++) {
        const int a = SWH(base + q * MS);
        Xa[a] = XX[q]; Ya[a] = YY[q];
    }
    __syncthreads();
}

// ---------------- forward radix-16 pass, fp16 workspace (k_all, unchanged) ----------------
template <int MS, int TSOF, int TBOF>
__device__ void pass16hf(__half2* __restrict__ s, const float2* __restrict__ tw) {
    const int tid = threadIdx.x;
#pragma unroll 1
    for (int i = 0; i < 2; i++) {
        const int tau  = tid + i * NTH;
        const int j    = tau & (MS - 1);
        const int g    = tau / MS;
        const int base = g * (16 * MS) + j;
        float2 x[16];
#pragma unroll
        for (int q = 0; q < 16; q++) x[q] = __half22float2(s[SWH(base + q * MS)]);
        float2 tb = tw[TBOF + j];
        bf_fwd(x[0], x[4], x[8], x[12], tb);
#pragma unroll
        for (int q0 = 1; q0 < 4; q0++) {
            float2 wb = cmul(tb, c16(q0));
            bf_fwd(x[q0], x[q0 + 4], x[q0 + 8], x[q0 + 12], wb);
        }
        float2 ws = tw[TSOF + j];
#pragma unroll
        for (int q1 = 0; q1 < 4; q1++)
            bf_fwd(x[4 * q1], x[4 * q1 + 1], x[4 * q1 + 2], x[4 * q1 + 3], ws);
#pragma unroll
        for (int q = 0; q < 16; q++)
            s[SWH(base + q * MS)] = __floats2half2_rn(x[q].x, x[q].y);
    }
    __syncthreads();
}

__device__ __forceinline__ void fwd_core_h(__half2* dat, const float2* tw) {
    pass16hf<1024, T1024S, T1024B>(dat, tw);
    pass16hf<64,   T64S,   T64B>(dat, tw);
    pass16hf<4,    T4S,    T4B>(dat, tw);
}

__device__ __forceinline__ void last_fwd_h(const __half2* dat, int k0, float2& b0, float2& b1,
                                           float2& b2, float2& b3) {
    float2 x[4];
    ld4h(dat + SWH(k0), x);
    float2 p02 = cadd(x[0], x[2]), m02 = csub(x[0], x[2]);
    float2 p13 = cadd(x[1], x[3]), m13 = csub(x[1], x[3]);
    float2 ni  = make_float2(m13.y, -m13.x);
    b0 = cadd(p02, p13); b1 = cadd(m02, ni);
    b2 = csub(p02, p13); b3 = csub(m02, ni);
}

// ---------------- k_all: S (2) + templates (100, wait on S) + xi (64) — R15 verbatim ----------------
__global__ void __launch_bounds__(NTH, 2) k_all(const float* __restrict__ Tm,
                                                const float* __restrict__ xi,
                                                const float* __restrict__ Sm) {
    extern __shared__ char smraw[];
    __half2* dat = (__half2*)smraw;
    float2*  tw  = (float2*)(smraw + (size_t)LL * 4);
    __shared__ int s_ok;
    const int tid = threadIdx.x, bi = blockIdx.x;
    const bool isS = (bi >= 164);

    for (int i = tid; i < TWTOT; i += NTH) {
        float2 v = twval(i);
        tw[i] = v;
        if (isS) g_twf[i] = v;
    }
    if (bi < 100) {
        const float* src = Tm + (size_t)bi * KTL;
        for (int t = tid; t < LL; t += NTH)
            dat[SWH(t)] = __floats2half2_rn(t < KTL ? src[t] : 0.f, 0.f);
    } else if (bi < 164) {
        const float* src = xi + (size_t)(bi - 100) * LL;
        for (int t = tid; t < LL; t += NTH)
            dat[SWH(t)] = __floats2half2_rn(src[t], 0.f);
    } else {
        const float* src = Sm + (size_t)(bi - 164) * LL;
        for (int t = tid; t < LL; t += NTH)
            dat[SWH(t)] = __floats2half2_rn(src[t], 0.f);
    }
    __syncthreads();
    fwd_core_h(dat, tw);

    if (isS) {
        float2* out = g_S[bi - 164];
#pragma unroll 1
        for (int i = 0; i < 8; i++) {
            const int k0 = 4 * (tid + i * NTH);
            float2 b0, b1, b2, b3;
            last_fwd_h(dat, k0, b0, b1, b2, b3);
            float4* o4 = (float4*)(out + k0);
            o4[0] = make_float4(b0.x, b0.y, b1.x, b1.y);
            o4[1] = make_float4(b2.x, b2.y, b3.x, b3.y);
        }
        __threadfence();
        __syncthreads();
        if (tid == 0) atomicAdd(&g_Sdone, 1);
    } else if (bi >= 100) {
        __half2* out = g_D[bi - 100];
#pragma unroll 1
        for (int i = 0; i < 8; i++) {
            const int k0 = 4 * (tid + i * NTH);
            float2 b0, b1, b2, b3;
            last_fwd_h(dat, k0, b0, b1, b2, b3);
            st4h(out + k0, b0, b1, b2, b3);
        }
    } else {
        if (tid == 0) {
            while (*(volatile int*)&g_Sdone < 2) __nanosleep(40);
            s_ok = 1;
        }
        __syncthreads();
        __threadfence();
        const float2* Sc = g_S[bi & 1];
        __half2* out = g_H[bi];
#pragma unroll 1
        for (int i = 0; i < 8; i++) {
            const int k0 = 4 * (tid + i * NTH);
            float2 b0, b1, b2, b3;
            last_fwd_h(dat, k0, b0, b1, b2, b3);
            const float4* s4 = (const float4*)(Sc + k0);
            float4 sA = s4[0], sB = s4[1];
            st4h(out + k0,
                 cmul(b0, make_float2(sA.x, sA.y)),
                 cmul(b1, make_float2(sA.z, sA.w)),
                 cmul(b2, make_float2(sB.x, sB.y)),
                 cmul(b3, make_float2(sB.z, sB.w)));
        }
    }
}

// ---------------- inverse: packed-SoA half2 middle passes, fp32 final ----------------
__global__ void __launch_bounds__(NTH, 2) k_inv(const float* __restrict__ hh) {
    extern __shared__ char smraw[];
    __half2* Xa   = (__half2*)smraw;                           // 32 KB (re pairs)
    __half2* Ya   = (__half2*)(smraw + 32768);                 // 32 KB (im pairs)
    float2*  tw32 = (float2*)(smraw + 65536);                  // 16 KB (final-pass tw)
    __half2* twp  = (__half2*)(smraw + 65536 + 16384);         // 1.6 KB (packed forms)
    const int tid = threadIdx.x;
    const int n = blockIdx.x, b = blockIdx.y;
    if (tid == 0 && n == 0 && b == 0) g_Sdone = 0;             // reset for next replay

    // twiddles: fp32 entries 0..2047 (T1024S/T1024B) + packed broadcast forms
    for (int k = tid; k < 2048; k += NTH) tw32[k] = g_twf[k];
    if (tid < EPTOT) {
        int src = (tid < 4)  ? (T4S + tid)
                : (tid < 8)  ? (T4B + tid - 4)
                : (tid < 72) ? (T64S + tid - 8)
                             : (T64B + tid - 72);
        float2 w = g_twf[src];
        twp[3 * tid]     = __float2half2_rn(w.x);
        twp[3 * tid + 1] = __float2half2_rn(w.y);
        twp[3 * tid + 2] = __float2half2_rn(-w.y);
    }

    const __half2* __restrict__ D0 = g_D[b * 2 + 0];
    const __half2* __restrict__ D1 = g_D[b * 2 + 1];
    const __half2* __restrict__ H0 = g_H[n * 2 + 0];
    const __half2* __restrict__ H1 = g_H[n * 2 + 1];

    // pointwise (fp32) + inverse m=1 stage, for bin groups k0 and k0+8192;
    // results packed SoA: X=(re_k, re_{k+8192}), Y=(im_k, im_{k+8192})
#pragma unroll 1
    for (int i = 0; i < 4; i++) {
        const int k0 = 4 * (tid + i * NTH);      // [0, 8192)
        float2 vA[4], vB[4];
#pragma unroll
        for (int half = 0; half < 2; half++) {
            const int kk = k0 + half * 8192;
            float2 d[4], e[4], h[4], f[4];
            ld4h(D0 + kk, d);
            ld4h(D1 + kk, e);
            ld4h(H0 + kk, h);
            ld4h(H1 + kk, f);
            float2 v[4];
#pragma unroll
            for (int q = 0; q < 4; q++) {
                float2 GA = cmulcj(d[q], h[q]);
                float2 GE = cmulcj(e[q], f[q]);
                v[q] = make_float2(GA.x - GE.y, GA.y + GE.x);
            }
            float2 p02 = cadd(v[0], v[2]), m02 = csub(v[0], v[2]);
            float2 p13 = cadd(v[1], v[3]), m13 = csub(v[1], v[3]);
            float2 pi  = make_float2(-m13.y, m13.x);
            float2* dst = half ? vB : vA;
            dst[0] = cadd(p02, p13);
            dst[1] = cadd(m02, pi);
            dst[2] = csub(p02, p13);
            dst[3] = csub(m02, pi);
        }
        const int a = SWH(k0);
        uint4 ux, uy;
        *reinterpret_cast<__half2*>(&ux.x) = __floats2half2_rn(vA[0].x, vB[0].x);
        *reinterpret_cast<__half2*>(&ux.y) = __floats2half2_rn(vA[1].x, vB[1].x);
        *reinterpret_cast<__half2*>(&ux.z) = __floats2half2_rn(vA[2].x, vB[2].x);
        *reinterpret_cast<__half2*>(&ux.w) = __floats2half2_rn(vA[3].x, vB[3].x);
        *reinterpret_cast<__half2*>(&uy.x) = __floats2half2_rn(vA[0].y, vB[0].y);
        *reinterpret_cast<__half2*>(&uy.y) = __floats2half2_rn(vA[1].y, vB[1].y);
        *reinterpret_cast<__half2*>(&uy.z) = __floats2half2_rn(vA[2].y, vB[2].y);
        *reinterpret_cast<__half2*>(&uy.w) = __floats2half2_rn(vA[3].y, vB[3].y);
        *reinterpret_cast<uint4*>(Xa + a) = ux;
        *reinterpret_cast<uint4*>(Ya + a) = uy;
    }
    __syncthreads();

    // packed middle passes: stages (4,16) then (64,256) — 2 bins per instruction
    pass16p<4,  E4S,  E4B>(Xa, Ya, twp);
    pass16p<64, E64S, E64B>(Xa, Ya, twp);

    // final pass (1024,4096) in fp32 registers; unpack pairs (q, q+8); fold max
    float mA = -3.4e38f, mE = -3.4e38f;
#pragma unroll 1
    for (int i = 0; i < 2; i++) {
        const int j = tid + i * NTH;             // [0, 1024)
        float2 x[16];
#pragma unroll
        for (int q = 0; q < 8; q++) {
            const int a = SWH(j + 1024 * q);
            __half2 hx = Xa[a], hy = Ya[a];
            x[q]     = make_float2(__low2float(hx),  __low2float(hy));
            x[q + 8] = make_float2(__high2float(hx), __high2float(hy));
        }
        float2 ws = tw32[j];                     // T1024S
#pragma unroll
        for (int q1 = 0; q1 < 4; q1++)
            bf_inv(x[4 * q1], x[4 * q1 + 1], x[4 * q1 + 2], x[4 * q1 + 3], ws);
        float2 tb = tw32[1024 + j];              // T1024B
        bf_inv(x[0], x[4], x[8], x[12], tb);
#pragma unroll
        for (int q0 = 1; q0 < 4; q0++) {
            float2 wb = cmul(tb, c16(q0));
            bf_inv(x[q0], x[q0 + 4], x[q0 + 8], x[q0 + 12], wb);
        }
#pragma unroll
        for (int q = 0; q < 16; q++) {
            mA = fmaxf(mA, x[q].x);
            mE = fmaxf(mE, x[q].y);
        }
    }
#pragma unroll
    for (int o = 16; o > 0; o >>= 1) {
        mA = fmaxf(mA, __shfl_xor_sync(0xffffffffu, mA, o));
        mE = fmaxf(mE, __shfl_xor_sync(0xffffffffu, mE, o));
    }
    __shared__ float rA[NTH / 32], rE[NTH / 32];
    if ((tid & 31) == 0) { rA[tid >> 5] = mA; rE[tid >> 5] = mE; }
    __syncthreads();
    if (tid == 0) {
        for (int i = 1; i < NTH / 32; i++) { mA = fmaxf(mA, rA[i]); mE = fmaxf(mE, rE[i]); }
        const float sc = 1.f / (float)LL;
        g_z[(b * 2 + 0) * NT + n] = mA * sc / hh[n * 2 + 0];
        g_z[(b * 2 + 1) * NT + n] = mE * sc / hh[n * 2 + 1];
    }
}

// ---------------- tiny CNN + MLP head (R15 verbatim) ----------------
__device__ __forceinline__ float sigm(float x) { return 1.f / (1.f + __expf(-x)); }

__global__ void k_head(const float* __restrict__ W1, const float* __restrict__ b1,
                       const float* __restrict__ W2, const float* __restrict__ b2,
                       const float* __restrict__ W3, const float* __restrict__ b3,
                       const float* __restrict__ W4, const float* __restrict__ b4,
                       float* __restrict__ out) {
    __shared__ float zb[2][NT];
    __shared__ float sW1[96],  sb1[16];
    __shared__ float sW2[1536], sb2[32];
    __shared__ float sW3[4096], sb3[32];
    __shared__ float sW4[64],   sb4[2];
    __shared__ float p1[16][16];
    __shared__ float p2[32][4];
    __shared__ float h1[32];
    const int b = blockIdx.x, tid = threadIdx.x;

    for (int i = tid; i < 2 * NT; i += 128) zb[i / NT][i % NT] = g_z[b * 2 * NT + i];
    if (tid < 96) sW1[tid] = W1[tid];
    if (tid < 16) sb1[tid] = b1[tid];
    for (int i = tid; i < 1536; i += 128) sW2[i] = W2[i];
    if (tid < 32) sb2[tid] = b2[tid];
    for (int i = tid; i < 4096; i += 128) sW3[i] = W3[i];
    if (tid >= 32 && tid < 64) sb3[tid - 32] = b3[tid - 32];
    if (tid >= 64 && tid < 128) sW4[tid - 64] = W4[tid - 64];
    if (tid >= 96 && tid < 98) sb4[tid - 96] = b4[tid - 96];
    __syncthreads();

    for (int i = tid; i < 16 * 16; i += 128) {
        int o = i >> 4, tp = i & 15;
        float mx = -3.4e38f;
        for (int q = 0; q < 3; q++) {
            int t = 3 * tp + q;
            float acc = sb1[o];
            for (int c = 0; c < 2; c++)
                for (int j = 0; j < 3; j++) acc += zb[c][t + j] * sW1[(o * 2 + c) * 3 + j];
            mx = fmaxf(mx, sigm(acc));
        }
        p1[o][tp] = mx;
    }
    __syncthreads();
    for (int i = tid; i < 32 * 4; i += 128) {
        int o = i >> 2, tp = i & 3;
        float mx = -3.4e38f;
        for (int q = 0; q < 3; q++) {
            int t = 3 * tp + q;
            float acc = sb2[o];
            for (int ci = 0; ci < 16; ci++)
                for (int j = 0; j < 3; j++) acc += p1[ci][t + j] * sW2[(o * 16 + ci) * 3 + j];
            mx = fmaxf(mx, sigm(acc));
        }
        p2[o][tp] = mx;
    }
    __syncthreads();
    if (tid < 32) {
        float acc = sb3[tid];
        for (int i = 0; i < 128; i++) acc += p2[i >> 2][i & 3] * sW3[tid * 128 + i];
        h1[tid] = fmaxf(acc, 0.f);
    }
    __syncthreads();
    if (tid < 2) {
        float acc = sb4[tid];
        for (int i = 0; i < 32; i++) acc += h1[i] * sW4[tid * 32 + i];
        out[b * 2 + tid] = acc;
    }
}

// ---------------- launch ----------------
extern "C" void kernel_launch(void* const* d_in, const int* in_sizes, int n_in,
                              void* d_out, int out_size) {
    const float* xi = (const float*)d_in[0];
    const float* S  = (const float*)d_in[1];
    const float* Tm = (const float*)d_in[2];
    const float* hh = (const float*)d_in[3];
    const float* W1 = (const float*)d_in[4];
    const float* b1 = (const float*)d_in[5];
    const float* W2 = (const float*)d_in[6];
    const float* b2 = (const float*)d_in[7];
    const float* W3 = (const float*)d_in[8];
    const float* b3 = (const float*)d_in[9];
    const float* W4 = (const float*)d_in[10];
    const float* b4 = (const float*)d_in[11];

    const size_t sha = (size_t)LL * 4 + (size_t)TWTOT * sizeof(float2);        // ~81 KB (k_all)
    const size_t shv = 65536 + 16384 + (size_t)(3 * EPTOT) * sizeof(__half2);  // ~83.5 KB (k_inv)
    cudaFuncSetAttribute(k_all, cudaFuncAttributeMaxDynamicSharedMemorySize, (int)sha);
    cudaFuncSetAttribute(k_inv, cudaFuncAttributeMaxDynamicSharedMemorySize, (int)shv);

    k_all<<<166, NTH, sha>>>(Tm, xi, S);
    dim3 gi(NT, NB);
    k_inv<<<gi, NTH, shv>>>(hh);
    k_head<<<NB, 128>>>(W1, b1, W2, b2, W3, b3, W4, b4, (float*)d_out);
}

// round 17
// speedup vs baseline: 1.9503x; 1.0653x over previous
#include <cuda_runtime.h>
#include <cuda_fp16.h>
#include <math.h>

#define LL   16384
#define HLL  8192
#define KTL  4096
#define NB   32
#define NT   50
#define NTH  512

// compact twiddle tables (identity: tw_big[j+q0*MS] = tw_base[j]*C[q0])
#define T1024S 0
#define T1024B 1024
#define T64S   2048
#define T64B   2112
#define T4S    2176
#define T4B    2180
#define TWTOT  2184

// packed (broadcast-form) table entry indices for k_inv middle passes
#define E4S  0
#define E4B  4
#define E64S 8
#define E64B 72
#define EPTOT 136

// ---------------- device scratch ----------------
// g_H/g_D: SoA pair-packed spectra. [row][0=re,1=im][k], each __half2 holds
// (val_k, val_{k+8192}).
__device__ float2  g_S[2][LL];            // S spectra (fp32, natural order)
__device__ __half2 g_H[100][2][HLL];      // H' = S*H template spectra
__device__ __half2 g_D[64][2][HLL];       // Xi spectra
__device__ float   g_z[NB * 2 * NT];
__device__ float2  g_twf[TWTOT];
__device__ int     g_Sdone = 0;           // S-spectra completion counter

// swizzle (conflict-free for strides 1,4,64,1024; preserves low 2 bits)
#define SWH(k) ((k) ^ ((((k) >> 6) & 7) << 2))

// ---------------- complex helpers (fp32) ----------------
__device__ __forceinline__ float2 cadd(float2 a, float2 b) { return make_float2(a.x + b.x, a.y + b.y); }
__device__ __forceinline__ float2 csub(float2 a, float2 b) { return make_float2(a.x - b.x, a.y - b.y); }
__device__ __forceinline__ float2 cmul(float2 a, float2 b) {
    return make_float2(a.x * b.x - a.y * b.y, a.x * b.y + a.y * b.x);
}
__device__ __forceinline__ float2 cmulcj(float2 a, float2 b) {
    return make_float2(a.x * b.x + a.y * b.y, a.y * b.x - a.x * b.y);
}

// C[q0] = exp(-2*pi*i*q0/16)
__device__ __forceinline__ float2 c16(int q0) {
    if (q0 == 1) return make_float2(0.9238795325112867f, -0.3826834323650898f);
    if (q0 == 2) return make_float2(0.7071067811865476f, -0.7071067811865476f);
    return make_float2(0.3826834323650898f, -0.9238795325112867f);
}

// ---------------- 16B vector helpers ----------------
__device__ __forceinline__ void ld4h(const __half2* __restrict__ p, float2 v[4]) {
    uint4 u = *reinterpret_cast<const uint4*>(p);
    v[0] = __half22float2(*reinterpret_cast<__half2*>(&u.x));
    v[1] = __half22float2(*reinterpret_cast<__half2*>(&u.y));
    v[2] = __half22float2(*reinterpret_cast<__half2*>(&u.z));
    v[3] = __half22float2(*reinterpret_cast<__half2*>(&u.w));
}

// load/store 4 raw half2 (one 16B transaction)
__device__ __forceinline__ void ld4x(const __half2* __restrict__ p, __half2 v[4]) {
    uint4 u = *reinterpret_cast<const uint4*>(p);
    v[0] = *reinterpret_cast<__half2*>(&u.x);
    v[1] = *reinterpret_cast<__half2*>(&u.y);
    v[2] = *reinterpret_cast<__half2*>(&u.z);
    v[3] = *reinterpret_cast<__half2*>(&u.w);
}
__device__ __forceinline__ void st4x(__half2* __restrict__ p, const __half2 v[4]) {
    uint4 u;
    *reinterpret_cast<__half2*>(&u.x) = v[0];
    *reinterpret_cast<__half2*>(&u.y) = v[1];
    *reinterpret_cast<__half2*>(&u.z) = v[2];
    *reinterpret_cast<__half2*>(&u.w) = v[3];
    *reinterpret_cast<uint4*>(p) = u;
}

// forward DIF radix-4 (fp32, k_all)
__device__ __forceinline__ void bf_fwd(float2& x0, float2& x1, float2& x2, float2& x3, float2 w1) {
    float2 p02 = cadd(x0, x2), m02 = csub(x0, x2);
    float2 p13 = cadd(x1, x3), m13 = csub(x1, x3);
    float2 ni  = make_float2(m13.y, -m13.x);
    float2 b0 = cadd(p02, p13), b1 = cadd(m02, ni);
    float2 b2 = csub(p02, p13), b3 = csub(m02, ni);
    float2 w2 = make_float2(w1.x * w1.x - w1.y * w1.y, 2.f * w1.x * w1.y);
    float2 w3 = cmul(w2, w1);
    x0 = b0; x1 = cmul(b1, w1); x2 = cmul(b2, w2); x3 = cmul(b3, w3);
}

// inverse DIT radix-4 (fp32, final pass)
__device__ __forceinline__ void bf_inv(float2& x0, float2& x1, float2& x2, float2& x3, float2 w1) {
    w1.y = -w1.y;
    float2 w2 = make_float2(w1.x * w1.x - w1.y * w1.y, 2.f * w1.x * w1.y);
    float2 w3 = cmul(w2, w1);
    float2 a1 = cmul(x1, w1), a2 = cmul(x2, w2), a3 = cmul(x3, w3);
    float2 p02 = cadd(x0, a2), m02 = csub(x0, a2);
    float2 p13 = cadd(a1, a3), m13 = csub(a1, a3);
    float2 pi  = make_float2(-m13.y, m13.x);
    x0 = cadd(p02, p13); x1 = cadd(m02, pi);
    x2 = csub(p02, p13); x3 = csub(m02, pi);
}

// ---------------- twiddle generation (fp32 sincospif) ----------------
__device__ __forceinline__ float2 twval(int i) {
    int j; float den;
    if      (i < T1024B) { j = i;          den = 4096.f;  }
    else if (i < T64S)   { j = i - T1024B; den = 16384.f; }
    else if (i < T64B)   { j = i - T64S;   den = 256.f;   }
    else if (i < T4S)    { j = i - T64B;   den = 1024.f;  }
    else if (i < T4B)    { j = i - T4S;    den = 16.f;    }
    else                 { j = i - T4B;    den = 64.f;    }
    float a = -2.f * (float)j / den;
    float s, c;
    sincospif(a, &s, &c);
    return make_float2(c, s);
}

// ---------------- packed half2 butterfly machinery (k_inv) ----------------
__device__ __forceinline__ void prep_forms(__half2* F, __half2 RR, __half2 II, __half2 NII) {
    F[0] = RR; F[1] = II; F[2] = NII;
    F[3] = __hfma2(II, NII, __hmul2(RR, RR));
    __half2 t = __hmul2(RR, II);
    F[4] = __hadd2(t, t);
    F[5] = __hneg2(F[4]);
    F[6] = __hfma2(F[4], NII, __hmul2(F[3], RR));
    F[7] = __hfma2(F[4], RR, __hmul2(F[3], II));
    F[8] = __hneg2(F[7]);
}

template <int S>
__device__ __forceinline__ void bfp_inv(__half2* X, __half2* Y, const __half2 (&F)[9]) {
    __half2 a1X = __hfma2(Y[S],     F[1], __hmul2(X[S],     F[0]));
    __half2 a1Y = __hfma2(X[S],     F[2], __hmul2(Y[S],     F[0]));
    __half2 a2X = __hfma2(Y[2 * S], F[4], __hmul2(X[2 * S], F[3]));
    __half2 a2Y = __hfma2(X[2 * S], F[5], __hmul2(Y[2 * S], F[3]));
    __half2 a3X = __hfma2(Y[3 * S], F[7], __hmul2(X[3 * S], F[6]));
    __half2 a3Y = __hfma2(X[3 * S], F[8], __hmul2(Y[3 * S], F[6]));
    __half2 p02X = __hadd2(X[0], a2X), p02Y = __hadd2(Y[0], a2Y);
    __half2 m02X = __hsub2(X[0], a2X), m02Y = __hsub2(Y[0], a2Y);
    __half2 p13X = __hadd2(a1X, a3X),  p13Y = __hadd2(a1Y, a3Y);
    __half2 m13X = __hsub2(a1X, a3X),  m13Y = __hsub2(a1Y, a3Y);
    X[0]     = __hadd2(p02X, p13X); Y[0]     = __hadd2(p02Y, p13Y);
    X[S]     = __hsub2(m02X, m13Y); Y[S]     = __hadd2(m02Y, m13X);
    X[2 * S] = __hsub2(p02X, p13X); Y[2 * S] = __hsub2(p02Y, p13Y);
    X[3 * S] = __hadd2(m02X, m13Y); Y[3 * S] = __hsub2(m02Y, m13X);
}

template <int MS, int ES, int EB>
__device__ void pass16p(__half2* __restrict__ Xa, __half2* __restrict__ Ya,
                        const __half2* __restrict__ twp) {
    const int tid  = threadIdx.x;
    const int j    = tid & (MS - 1);
    const int g    = tid / MS;
    const int base = g * (16 * MS) + j;
    __half2 XX[16], YY[16];
#pragma unroll
    for (int q = 0; q < 16; q++) {
        const int a = SWH(base + q * MS);
        XX[q] = Xa[a]; YY[q] = Ya[a];
    }
    {
        __half2 F[9];
        prep_forms(F, twp[3 * (ES + j)], twp[3 * (ES + j) + 1], twp[3 * (ES + j) + 2]);
        bfp_inv<1>(XX + 0,  YY + 0,  F);
        bfp_inv<1>(XX + 4,  YY + 4,  F);
        bfp_inv<1>(XX + 8,  YY + 8,  F);
        bfp_inv<1>(XX + 12, YY + 12, F);
    }
    {
        __half2 BR = twp[3 * (EB + j)], BI = twp[3 * (EB + j) + 1], BNI = twp[3 * (EB + j) + 2];
        __half2 F[9];
        prep_forms(F, BR, BI, BNI);
        bfp_inv<4>(XX + 0, YY + 0, F);
#pragma unroll
        for (int q0 = 1; q0 < 4; q0++) {
            const float2 c = c16(q0);
            const __half2 CR  = __float2half2_rn(c.x);
            const __half2 CI  = __float2half2_rn(c.y);
            const __half2 NCI = __float2half2_rn(-c.y);
            __half2 RRb  = __hfma2(BI, NCI, __hmul2(BR, CR));
            __half2 IIb  = __hfma2(BR, CI,  __hmul2(BI, CR));
            __half2 NIIb = __hneg2(IIb);
            prep_forms(F, RRb, IIb, NIIb);
            bfp_inv<4>(XX + q0, YY + q0, F);
        }
    }
#pragma unroll
    for (int q = 0; q < 16; q++) {
        const int a = SWH(base + q * MS);
        Xa[a] = XX[q]; Ya[a] = YY[q];
    }
    __syncthreads();
}

// ---------------- forward radix-16 pass, fp16 workspace (k_all) ----------------
template <int MS, int TSOF, int TBOF>
__device__ void pass16hf(__half2* __restrict__ s, const float2* __restrict__ tw) {
    const int tid = threadIdx.x;
#pragma unroll 1
    for (int i = 0; i < 2; i++) {
        const int tau  = tid + i * NTH;
        const int j    = tau & (MS - 1);
        const int g    = tau / MS;
        const int base = g * (16 * MS) + j;
        float2 x[16];
#pragma unroll
        for (int q = 0; q < 16; q++) x[q] = __half22float2(s[SWH(base + q * MS)]);
        float2 tb = tw[TBOF + j];
        bf_fwd(x[0], x[4], x[8], x[12], tb);
#pragma unroll
        for (int q0 = 1; q0 < 4; q0++) {
            float2 wb = cmul(tb, c16(q0));
            bf_fwd(x[q0], x[q0 + 4], x[q0 + 8], x[q0 + 12], wb);
        }
        float2 ws = tw[TSOF + j];
#pragma unroll
        for (int q1 = 0; q1 < 4; q1++)
            bf_fwd(x[4 * q1], x[4 * q1 + 1], x[4 * q1 + 2], x[4 * q1 + 3], ws);
#pragma unroll
        for (int q = 0; q < 16; q++)
            s[SWH(base + q * MS)] = __floats2half2_rn(x[q].x, x[q].y);
    }
    __syncthreads();
}

__device__ __forceinline__ void fwd_core_h(__half2* dat, const float2* tw) {
    pass16hf<1024, T1024S, T1024B>(dat, tw);
    pass16hf<64,   T64S,   T64B>(dat, tw);
    pass16hf<4,    T4S,    T4B>(dat, tw);
}

__device__ __forceinline__ void last_fwd_h(const __half2* dat, int k0, float2& b0, float2& b1,
                                           float2& b2, float2& b3) {
    float2 x[4];
    ld4h(dat + SWH(k0), x);
    float2 p02 = cadd(x[0], x[2]), m02 = csub(x[0], x[2]);
    float2 p13 = cadd(x[1], x[3]), m13 = csub(x[1], x[3]);
    float2 ni  = make_float2(m13.y, -m13.x);
    b0 = cadd(p02, p13); b1 = cadd(m02, ni);
    b2 = csub(p02, p13); b3 = csub(m02, ni);
}

// ---------------- k_all: S (2) + templates (100, wait on S) + xi (64) ----------------
// Outputs g_H / g_D in SoA pair-packed form.
__global__ void __launch_bounds__(NTH, 2) k_all(const float* __restrict__ Tm,
                                                const float* __restrict__ xi,
                                                const float* __restrict__ Sm) {
    extern __shared__ char smraw[];
    __half2* dat = (__half2*)smraw;
    float2*  tw  = (float2*)(smraw + (size_t)LL * 4);
    __shared__ int s_ok;
    const int tid = threadIdx.x, bi = blockIdx.x;
    const bool isS = (bi >= 164);

    for (int i = tid; i < TWTOT; i += NTH) {
        float2 v = twval(i);
        tw[i] = v;
        if (isS) g_twf[i] = v;
    }
    if (bi < 100) {
        const float* src = Tm + (size_t)bi * KTL;
        for (int t = tid; t < LL; t += NTH)
            dat[SWH(t)] = __floats2half2_rn(t < KTL ? src[t] : 0.f, 0.f);
    } else if (bi < 164) {
        const float* src = xi + (size_t)(bi - 100) * LL;
        for (int t = tid; t < LL; t += NTH)
            dat[SWH(t)] = __floats2half2_rn(src[t], 0.f);
    } else {
        const float* src = Sm + (size_t)(bi - 164) * LL;
        for (int t = tid; t < LL; t += NTH)
            dat[SWH(t)] = __floats2half2_rn(src[t], 0.f);
    }
    __syncthreads();
    fwd_core_h(dat, tw);

    if (isS) {
        float2* out = g_S[bi - 164];
#pragma unroll 1
        for (int i = 0; i < 8; i++) {
            const int k0 = 4 * (tid + i * NTH);
            float2 b0, b1, b2, b3;
            last_fwd_h(dat, k0, b0, b1, b2, b3);
            float4* o4 = (float4*)(out + k0);
            o4[0] = make_float4(b0.x, b0.y, b1.x, b1.y);
            o4[1] = make_float4(b2.x, b2.y, b3.x, b3.y);
        }
        __threadfence();
        __syncthreads();
        if (tid == 0) atomicAdd(&g_Sdone, 1);
    } else if (bi >= 100) {
        __half2* outre = g_D[bi - 100][0];
        __half2* outim = g_D[bi - 100][1];
#pragma unroll 1
        for (int i = 0; i < 4; i++) {
            const int k0 = 4 * (tid + i * NTH);   // [0, 8192)
            float2 a[4], bq[4];
            last_fwd_h(dat, k0,        a[0],  a[1],  a[2],  a[3]);
            last_fwd_h(dat, k0 + HLL,  bq[0], bq[1], bq[2], bq[3]);
            __half2 r[4], im[4];
#pragma unroll
            for (int q = 0; q < 4; q++) {
                r[q]  = __floats2half2_rn(a[q].x, bq[q].x);
                im[q] = __floats2half2_rn(a[q].y, bq[q].y);
            }
            st4x(outre + k0, r);
            st4x(outim + k0, im);
        }
    } else {
        if (tid == 0) {
            while (*(volatile int*)&g_Sdone < 2) __nanosleep(40);
            s_ok = 1;
        }
        __syncthreads();
        __threadfence();
        const float2* Sc = g_S[bi & 1];
        __half2* outre = g_H[bi][0];
        __half2* outim = g_H[bi][1];
#pragma unroll 1
        for (int i = 0; i < 4; i++) {
            const int k0 = 4 * (tid + i * NTH);   // [0, 8192)
            float2 a[4], bq[4];
            last_fwd_h(dat, k0,       a[0],  a[1],  a[2],  a[3]);
            last_fwd_h(dat, k0 + HLL, bq[0], bq[1], bq[2], bq[3]);
            const float4* sa = (const float4*)(Sc + k0);
            const float4* sb = (const float4*)(Sc + k0 + HLL);
            float4 sA0 = sa[0], sA1 = sa[1], sB0 = sb[0], sB1 = sb[1];
            a[0]  = cmul(a[0],  make_float2(sA0.x, sA0.y));
            a[1]  = cmul(a[1],  make_float2(sA0.z, sA0.w));
            a[2]  = cmul(a[2],  make_float2(sA1.x, sA1.y));
            a[3]  = cmul(a[3],  make_float2(sA1.z, sA1.w));
            bq[0] = cmul(bq[0], make_float2(sB0.x, sB0.y));
            bq[1] = cmul(bq[1], make_float2(sB0.z, sB0.w));
            bq[2] = cmul(bq[2], make_float2(sB1.x, sB1.y));
            bq[3] = cmul(bq[3], make_float2(sB1.z, sB1.w));
            __half2 r[4], im[4];
#pragma unroll
            for (int q = 0; q < 4; q++) {
                r[q]  = __floats2half2_rn(a[q].x, bq[q].x);
                im[q] = __floats2half2_rn(a[q].y, bq[q].y);
            }
            st4x(outre + k0, r);
            st4x(outim + k0, im);
        }
    }
}

// ---------------- inverse: fully packed pointwise + middle passes ----------------
__global__ void __launch_bounds__(NTH, 2) k_inv(const float* __restrict__ hh) {
    extern __shared__ char smraw[];
    __half2* Xa   = (__half2*)smraw;                           // 32 KB
    __half2* Ya   = (__half2*)(smraw + 32768);                 // 32 KB
    float2*  tw32 = (float2*)(smraw + 65536);                  // 16 KB
    __half2* twp  = (__half2*)(smraw + 65536 + 16384);         // 1.6 KB
    const int tid = threadIdx.x;
    const int n = blockIdx.x, b = blockIdx.y;
    if (tid == 0 && n == 0 && b == 0) g_Sdone = 0;

    for (int k = tid; k < 2048; k += NTH) tw32[k] = g_twf[k];
    if (tid < EPTOT) {
        int src = (tid < 4)  ? (T4S + tid)
                : (tid < 8)  ? (T4B + tid - 4)
                : (tid < 72) ? (T64S + tid - 8)
                             : (T64B + tid - 72);
        float2 w = g_twf[src];
        twp[3 * tid]     = __float2half2_rn(w.x);
        twp[3 * tid + 1] = __float2half2_rn(w.y);
        twp[3 * tid + 2] = __float2half2_rn(-w.y);
    }

    const __half2* __restrict__ D0r = g_D[b * 2 + 0][0];
    const __half2* __restrict__ D0i = g_D[b * 2 + 0][1];
    const __half2* __restrict__ D1r = g_D[b * 2 + 1][0];
    const __half2* __restrict__ D1i = g_D[b * 2 + 1][1];
    const __half2* __restrict__ H0r = g_H[n * 2 + 0][0];
    const __half2* __restrict__ H0i = g_H[n * 2 + 0][1];
    const __half2* __restrict__ H1r = g_H[n * 2 + 1][0];
    const __half2* __restrict__ H1i = g_H[n * 2 + 1][1];

    // fully packed pointwise (G = D*conj(H), pack GA + i*GE) + inverse m=1 stage
#pragma unroll 1
    for (int i = 0; i < 4; i++) {
        const int k0 = 4 * (tid + i * NTH);       // [0, 8192)
        __half2 d0r[4], d0i[4], d1r[4], d1i[4], h0r[4], h0i[4], h1r[4], h1i[4];
        ld4x(D0r + k0, d0r); ld4x(D0i + k0, d0i);
        ld4x(D1r + k0, d1r); ld4x(D1i + k0, d1i);
        ld4x(H0r + k0, h0r); ld4x(H0i + k0, h0i);
        ld4x(H1r + k0, h1r); ld4x(H1i + k0, h1i);
        __half2 vX[4], vY[4];
#pragma unroll
        for (int q = 0; q < 4; q++) {
            // GA = D0 * conj(H0):  re = d.r*h.r + d.i*h.i ; im = d.i*h.r - d.r*h.i
            __half2 gar = __hfma2(d0i[q], h0i[q], __hmul2(d0r[q], h0r[q]));
            __half2 gai = __hsub2(__hmul2(d0i[q], h0r[q]), __hmul2(d0r[q], h0i[q]));
            __half2 ger = __hfma2(d1i[q], h1i[q], __hmul2(d1r[q], h1r[q]));
            __half2 gei = __hsub2(__hmul2(d1i[q], h1r[q]), __hmul2(d1r[q], h1i[q]));
            vX[q] = __hsub2(gar, gei);            // re(GA + i*GE)
            vY[q] = __hadd2(gai, ger);            // im(GA + i*GE)
        }
        // inverse radix-4, m=1, w=1 (packed)
        __half2 p02X = __hadd2(vX[0], vX[2]), p02Y = __hadd2(vY[0], vY[2]);
        __half2 m02X = __hsub2(vX[0], vX[2]), m02Y = __hsub2(vY[0], vY[2]);
        __half2 p13X = __hadd2(vX[1], vX[3]), p13Y = __hadd2(vY[1], vY[3]);
        __half2 m13X = __hsub2(vX[1], vX[3]), m13Y = __hsub2(vY[1], vY[3]);
        __half2 oX[4], oY[4];
        oX[0] = __hadd2(p02X, p13X); oY[0] = __hadd2(p02Y, p13Y);
        oX[1] = __hsub2(m02X, m13Y); oY[1] = __hadd2(m02Y, m13X);
        oX[2] = __hsub2(p02X, p13X); oY[2] = __hsub2(p02Y, p13Y);
        oX[3] = __hadd2(m02X, m13Y); oY[3] = __hsub2(m02Y, m13X);
        st4x(Xa + SWH(k0), oX);
        st4x(Ya + SWH(k0), oY);
    }
    __syncthreads();

    pass16p<4,  E4S,  E4B>(Xa, Ya, twp);
    pass16p<64, E64S, E64B>(Xa, Ya, twp);

    // final pass (1024,4096) in fp32 registers; unpack pairs (q, q+8); fold max
    float mA = -3.4e38f, mE = -3.4e38f;
#pragma unroll 1
    for (int i = 0; i < 2; i++) {
        const int j = tid + i * NTH;
        float2 x[16];
#pragma unroll
        for (int q = 0; q < 8; q++) {
            const int a = SWH(j + 1024 * q);
            __half2 hx = Xa[a], hy = Ya[a];
            x[q]     = make_float2(__low2float(hx),  __low2float(hy));
            x[q + 8] = make_float2(__high2float(hx), __high2float(hy));
        }
        float2 ws = tw32[j];
#pragma unroll
        for (int q1 = 0; q1 < 4; q1++)
            bf_inv(x[4 * q1], x[4 * q1 + 1], x[4 * q1 + 2], x[4 * q1 + 3], ws);
        float2 tb = tw32[1024 + j];
        bf_inv(x[0], x[4], x[8], x[12], tb);
#pragma unroll
        for (int q0 = 1; q0 < 4; q0++) {
            float2 wb = cmul(tb, c16(q0));
            bf_inv(x[q0], x[q0 + 4], x[q0 + 8], x[q0 + 12], wb);
        }
#pragma unroll
        for (int q = 0; q < 16; q++) {
            mA = fmaxf(mA, x[q].x);
            mE = fmaxf(mE, x[q].y);
        }
    }
#pragma unroll
    for (int o = 16; o > 0; o >>= 1) {
        mA = fmaxf(mA, __shfl_xor_sync(0xffffffffu, mA, o));
        mE = fmaxf(mE, __shfl_xor_sync(0xffffffffu, mE, o));
    }
    __shared__ float rA[NTH / 32], rE[NTH / 32];
    if ((tid & 31) == 0) { rA[tid >> 5] = mA; rE[tid >> 5] = mE; }
    __syncthreads();
    if (tid == 0) {
        for (int i = 1; i < NTH / 32; i++) { mA = fmaxf(mA, rA[i]); mE = fmaxf(mE, rE[i]); }
        const float sc = 1.f / (float)LL;
        g_z[(b * 2 + 0) * NT + n] = mA * sc / hh[n * 2 + 0];
        g_z[(b * 2 + 1) * NT + n] = mE * sc / hh[n * 2 + 1];
    }
}

// ---------------- tiny CNN + MLP head (frozen) ----------------
__device__ __forceinline__ float sigm(float x) { return 1.f / (1.f + __expf(-x)); }

__global__ void k_head(const float* __restrict__ W1, const float* __restrict__ b1,
                       const float* __restrict__ W2, const float* __restrict__ b2,
                       const float* __restrict__ W3, const float* __restrict__ b3,
                       const float* __restrict__ W4, const float* __restrict__ b4,
                       float* __restrict__ out) {
    __shared__ float zb[2][NT];
    __shared__ float sW1[96],  sb1[16];
    __shared__ float sW2[1536], sb2[32];
    __shared__ float sW3[4096], sb3[32];
    __shared__ float sW4[64],   sb4[2];
    __shared__ float p1[16][16];
    __shared__ float p2[32][4];
    __shared__ float h1[32];
    const int b = blockIdx.x, tid = threadIdx.x;

    for (int i = tid; i < 2 * NT; i += 128) zb[i / NT][i % NT] = g_z[b * 2 * NT + i];
    if (tid < 96) sW1[tid] = W1[tid];
    if (tid < 16) sb1[tid] = b1[tid];
    for (int i = tid; i < 1536; i += 128) sW2[i] = W2[i];
    if (tid < 32) sb2[tid] = b2[tid];
    for (int i = tid; i < 4096; i += 128) sW3[i] = W3[i];
    if (tid >= 32 && tid < 64) sb3[tid - 32] = b3[tid - 32];
    if (tid >= 64 && tid < 128) sW4[tid - 64] = W4[tid - 64];
    if (tid >= 96 && tid < 98) sb4[tid - 96] = b4[tid - 96];
    __syncthreads();

    for (int i = tid; i < 16 * 16; i += 128) {
        int o = i >> 4, tp = i & 15;
        float mx = -3.4e38f;
        for (int q = 0; q < 3; q++) {
            int t = 3 * tp + q;
            float acc = sb1[o];
            for (int c = 0; c < 2; c++)
                for (int j = 0; j < 3; j++) acc += zb[c][t + j] * sW1[(o * 2 + c) * 3 + j];
            mx = fmaxf(mx, sigm(acc));
        }
        p1[o][tp] = mx;
    }
    __syncthreads();
    for (int i = tid; i < 32 * 4; i += 128) {
        int o = i >> 2, tp = i & 3;
        float mx = -3.4e38f;
        for (int q = 0; q < 3; q++) {
            int t = 3 * tp + q;
            float acc = sb2[o];
            for (int ci = 0; ci < 16; ci++)
                for (int j = 0; j < 3; j++) acc += p1[ci][t + j] * sW2[(o * 16 + ci) * 3 + j];
            mx = fmaxf(mx, sigm(acc));
        }
        p2[o][tp] = mx;
    }
    __syncthreads();
    if (tid < 32) {
        float acc = sb3[tid];
        for (int i = 0; i < 128; i++) acc += p2[i >> 2][i & 3] * sW3[tid * 128 + i];
        h1[tid] = fmaxf(acc, 0.f);
    }
    __syncthreads();
    if (tid < 2) {
        float acc = sb4[tid];
        for (int i = 0; i < 32; i++) acc += h1[i] * sW4[tid * 32 + i];
        out[b * 2 + tid] = acc;
    }
}

// ---------------- launch ----------------
extern "C" void kernel_launch(void* const* d_in, const int* in_sizes, int n_in,
                              void* d_out, int out_size) {
    const float* xi = (const float*)d_in[0];
    const float* S  = (const float*)d_in[1];
    const float* Tm = (const float*)d_in[2];
    const float* hh = (const float*)d_in[3];
    const float* W1 = (const float*)d_in[4];
    const float* b1 = (const float*)d_in[5];
    const float* W2 = (const float*)d_in[6];
    const float* b2 = (const float*)d_in[7];
    const float* W3 = (const float*)d_in[8];
    const float* b3 = (const float*)d_in[9];
    const float* W4 = (const float*)d_in[10];
    const float* b4 = (const float*)d_in[11];

    const size_t sha = (size_t)LL * 4 + (size_t)TWTOT * sizeof(float2);        // ~81 KB
    const size_t shv = 65536 + 16384 + (size_t)(3 * EPTOT) * sizeof(__half2);  // ~82.7 KB
    cudaFuncSetAttribute(k_all, cudaFuncAttributeMaxDynamicSharedMemorySize, (int)sha);
    cudaFuncSetAttribute(k_inv, cudaFuncAttributeMaxDynamicSharedMemorySize, (int)shv);

    k_all<<<166, NTH, sha>>>(Tm, xi, S);
    dim3 gi(NT, NB);
    k_inv<<<gi, NTH, shv>>>(hh);
    k_head<<<NB, 128>>>(W1, b1, W2, b2, W3, b3, W4, b4, (float*)d_out);
}